// round 1
// baseline (speedup 1.0000x reference)
#include <cuda_runtime.h>

typedef unsigned long long u64;

#define B_   16
#define C_   8
#define H_   512
#define W_   512
#define HW_  (H_*W_)
#define NPIX (B_*HW_)

__device__ unsigned int g_alive_count;

__global__ void k_zero() { g_alive_count = 0u; }

// Count alive cells (channel 3 > 0.1) over all batches. One float4 per thread.
__global__ void k_count(const float* __restrict__ x) {
    __shared__ unsigned int s_sum;
    if (threadIdx.x == 0) s_sum = 0u;
    __syncthreads();
    unsigned int gid  = blockIdx.x * blockDim.x + threadIdx.x;   // 1,048,576 total
    unsigned int b    = gid >> 16;                               // 65536 float4 per plane
    unsigned int off4 = gid & 65535u;
    const float4* p = reinterpret_cast<const float4*>(
        x + (size_t)b * (C_ * HW_) + (size_t)3 * HW_) + off4;
    float4 v = __ldg(p);
    unsigned int c = (v.x > 0.1f ? 1u : 0u) + (v.y > 0.1f ? 1u : 0u)
                   + (v.z > 0.1f ? 1u : 0u) + (v.w > 0.1f ? 1u : 0u);
    #pragma unroll
    for (int o = 16; o; o >>= 1) c += __shfl_down_sync(0xffffffffu, c, o);
    if ((threadIdx.x & 31) == 0) atomicAdd(&s_sum, c);
    __syncthreads();
    if (threadIdx.x == 0) atomicAdd(&g_alive_count, s_sum);
}

// ---- packed f32x2 helpers ----
__device__ __forceinline__ u64 pk2(float lo, float hi) {
    u64 r; asm("mov.b64 %0, {%1,%2};" : "=l"(r) : "f"(lo), "f"(hi)); return r;
}
__device__ __forceinline__ void upk2(u64 v, float& lo, float& hi) {
    asm("mov.b64 {%0,%1}, %2;" : "=f"(lo), "=f"(hi) : "l"(v));
}
__device__ __forceinline__ u64 fma2(u64 a, u64 b, u64 c) {
    u64 d; asm("fma.rn.f32x2 %0, %1, %2, %3;" : "=l"(d) : "l"(a), "l"(b), "l"(c));
    return d;
}
__device__ __forceinline__ u64 relu2(u64 v) {
    float a, b; upk2(v, a, b);
    a = fmaxf(a, 0.0f); b = fmaxf(b, 0.0f);
    return pk2(a, b);
}

__global__ __launch_bounds__(128)
void k_main(const float* __restrict__ x,
            const float* __restrict__ w1, const float* __restrict__ b1,
            const float* __restrict__ w2, const float* __restrict__ b2,
            const float* __restrict__ w3, const float* __restrict__ b3,
            const float* __restrict__ growth,
            float* __restrict__ out)
{
    // Weights duplicated as (w,w) f32x2 pairs so LDS feeds FFMA2 directly.
    __shared__ u64 sw1[32 * 24];
    __shared__ u64 sw2[32 * 32];
    __shared__ u64 sw3[8 * 32];
    __shared__ u64 sb1[32], sb2[32], sb3[8];
    __shared__ float s_gr;
    __shared__ float s_boostbase;

    const int tid = threadIdx.x;
    for (int i = tid; i < 32 * 24; i += 128) { float w = w1[i]; sw1[i] = pk2(w, w); }
    for (int i = tid; i < 32 * 32; i += 128) { float w = w2[i]; sw2[i] = pk2(w, w); }
    for (int i = tid; i < 8 * 32;  i += 128) { float w = w3[i]; sw3[i] = pk2(w, w); }
    if (tid < 32) { float v1 = b1[tid]; sb1[tid] = pk2(v1, v1);
                    float v2 = b2[tid]; sb2[tid] = pk2(v2, v2); }
    if (tid < 8)  { float v3 = b3[tid]; sb3[tid] = pk2(v3, v3); }
    if (tid == 0) {
        s_gr = growth[0];
        float ratio = (float)g_alive_count * (1.0f / (float)NPIX);
        s_boostbase = (ratio < 0.2f) ? 0.2f : 0.0f;
    }
    __syncthreads();

    // 2 horizontally adjacent pixels per thread; block = 16x8 threads -> 32x8 pixel tile
    const int tx = tid & 15, ty = tid >> 4;
    const int xi = (blockIdx.x * 16 + tx) * 2;
    const int yi = blockIdx.y * 8 + ty;
    const int b  = blockIdx.z;

    const float* xb = x + (size_t)b * (C_ * HW_);

    const bool ok_t = (yi > 0), ok_b = (yi < H_ - 1);
    const bool ok_l = (xi > 0), ok_r = (xi + 2 < W_);

    const float AT = 0.1f;
    u64 per[24];           // perceived: [x(8), sobel_x(8), sobel_y(8)], each packed (px0,px1)
    bool alive0 = false, alive1 = false;

    #pragma unroll
    for (int c = 0; c < 8; c++) {
        const float* pc = xb + (size_t)c * HW_ + (size_t)yi * W_ + xi;
        float v00, v01, v02, v03, v10, v11, v12, v13, v20, v21, v22, v23;
        v00 = (ok_t && ok_l) ? __ldg(pc - W_ - 1) : 0.0f;
        v01 =  ok_t          ? __ldg(pc - W_    ) : 0.0f;
        v02 =  ok_t          ? __ldg(pc - W_ + 1) : 0.0f;
        v03 = (ok_t && ok_r) ? __ldg(pc - W_ + 2) : 0.0f;
        v10 =  ok_l          ? __ldg(pc - 1)      : 0.0f;
        v11 =                  __ldg(pc);
        v12 =                  __ldg(pc + 1);
        v13 =  ok_r          ? __ldg(pc + 2)      : 0.0f;
        v20 = (ok_b && ok_l) ? __ldg(pc + W_ - 1) : 0.0f;
        v21 =  ok_b          ? __ldg(pc + W_    ) : 0.0f;
        v22 =  ok_b          ? __ldg(pc + W_ + 1) : 0.0f;
        v23 = (ok_b && ok_r) ? __ldg(pc + W_ + 2) : 0.0f;

        float sx0 = (v02 - v00) + 2.0f * (v12 - v10) + (v22 - v20);
        float sx1 = (v03 - v01) + 2.0f * (v13 - v11) + (v23 - v21);
        float sy0 = (v20 + 2.0f * v21 + v22) - (v00 + 2.0f * v01 + v02);
        float sy1 = (v21 + 2.0f * v22 + v23) - (v01 + 2.0f * v02 + v03);

        per[c]      = pk2(v11, v12);
        per[8 + c]  = pk2(sx0, sx1);
        per[16 + c] = pk2(sy0, sy1);

        if (c == 3) {
            // growth zone: any in-bounds 3x3 neighbor alive  (k/9 > 0.01 <=> k >= 1)
            alive0 = (v00 > AT) | (v01 > AT) | (v02 > AT)
                   | (v10 > AT) | (v11 > AT) | (v12 > AT)
                   | (v20 > AT) | (v21 > AT) | (v22 > AT);
            alive1 = (v01 > AT) | (v02 > AT) | (v03 > AT)
                   | (v11 > AT) | (v12 > AT) | (v13 > AT)
                   | (v21 > AT) | (v22 > AT) | (v23 > AT);
        }
    }

    // Layer 1: 24 -> 32, ReLU
    u64 h1[32];
    #pragma unroll
    for (int o = 0; o < 32; o++) {
        u64 acc = sb1[o];
        #pragma unroll
        for (int c = 0; c < 24; c++) acc = fma2(per[c], sw1[o * 24 + c], acc);
        h1[o] = relu2(acc);
    }

    // Layer 2: 32 -> 32, ReLU
    u64 h2[32];
    #pragma unroll
    for (int o = 0; o < 32; o++) {
        u64 acc = sb2[o];
        #pragma unroll
        for (int c = 0; c < 32; c++) acc = fma2(h1[c], sw2[o * 32 + c], acc);
        h2[o] = relu2(acc);
    }

    // Layer 3: 32 -> 8, scale, boost, residual, clip, write
    const float gr = s_gr;
    const float boost0 = alive0 ? s_boostbase : 0.0f;
    const float boost1 = alive1 ? s_boostbase : 0.0f;
    float* ob = out + (size_t)b * (C_ * HW_) + (size_t)yi * W_ + xi;

    #pragma unroll
    for (int o = 0; o < 8; o++) {
        u64 acc = sb3[o];
        #pragma unroll
        for (int c = 0; c < 32; c++) acc = fma2(h2[c], sw3[o * 32 + c], acc);
        float d0, d1; upk2(acc, d0, d1);
        d0 *= gr; d1 *= gr;
        if (o == 3) { d0 += boost0; d1 += boost1; }
        float xc0, xc1; upk2(per[o], xc0, xc1);   // per[0..7] holds center x values
        float n0 = fminf(fmaxf(xc0 + d0, -1.0f), 1.0f);
        float n1 = fminf(fmaxf(xc1 + d1, -1.0f), 1.0f);
        if (o == 3) { n0 = fmaxf(n0, 0.0f); n1 = fmaxf(n1, 0.0f); }
        *reinterpret_cast<float2*>(ob + (size_t)o * HW_) = make_float2(n0, n1);
    }
}

extern "C" void kernel_launch(void* const* d_in, const int* in_sizes, int n_in,
                              void* d_out, int out_size)
{
    const float* x  = (const float*)d_in[0];
    const float* w1 = (const float*)d_in[1];
    const float* b1 = (const float*)d_in[2];
    const float* w2 = (const float*)d_in[3];
    const float* b2 = (const float*)d_in[4];
    const float* w3 = (const float*)d_in[5];
    const float* b3 = (const float*)d_in[6];
    const float* gr = (const float*)d_in[7];
    float* out = (float*)d_out;

    k_zero<<<1, 1>>>();
    k_count<<<4096, 256>>>(x);                 // 1,048,576 float4 loads
    k_main<<<dim3(W_ / 32, H_ / 8, B_), 128>>>(x, w1, b1, w2, b2, w3, b3, gr, out);
}

// round 2
// speedup vs baseline: 1.1348x; 1.1348x over previous
#include <cuda_runtime.h>

typedef unsigned long long u64;

#define B_   16
#define C_   8
#define H_   512
#define W_   512
#define HW_  (H_*W_)
#define NPIX (B_*HW_)

__device__ unsigned int g_alive_count;

__global__ void k_zero() { g_alive_count = 0u; }

// Count alive cells (channel 3 > 0.1) over all batches. One float4 per thread.
__global__ void k_count(const float* __restrict__ x) {
    __shared__ unsigned int s_sum;
    if (threadIdx.x == 0) s_sum = 0u;
    __syncthreads();
    unsigned int gid  = blockIdx.x * blockDim.x + threadIdx.x;   // 1,048,576 total
    unsigned int b    = gid >> 16;                               // 65536 float4 per plane
    unsigned int off4 = gid & 65535u;
    const float4* p = reinterpret_cast<const float4*>(
        x + (size_t)b * (C_ * HW_) + (size_t)3 * HW_) + off4;
    float4 v = __ldg(p);
    unsigned int c = (v.x > 0.1f ? 1u : 0u) + (v.y > 0.1f ? 1u : 0u)
                   + (v.z > 0.1f ? 1u : 0u) + (v.w > 0.1f ? 1u : 0u);
    #pragma unroll
    for (int o = 16; o; o >>= 1) c += __shfl_down_sync(0xffffffffu, c, o);
    if ((threadIdx.x & 31) == 0) atomicAdd(&s_sum, c);
    __syncthreads();
    if (threadIdx.x == 0) atomicAdd(&g_alive_count, s_sum);
}

// ---- packed f32x2 helpers ----
__device__ __forceinline__ u64 pk2(float lo, float hi) {
    u64 r; asm("mov.b64 %0, {%1,%2};" : "=l"(r) : "f"(lo), "f"(hi)); return r;
}
__device__ __forceinline__ void upk2(u64 v, float& lo, float& hi) {
    asm("mov.b64 {%0,%1}, %2;" : "=f"(lo), "=f"(hi) : "l"(v));
}
__device__ __forceinline__ u64 fma2(u64 a, u64 b, u64 c) {
    u64 d; asm("fma.rn.f32x2 %0, %1, %2, %3;" : "=l"(d) : "l"(a), "l"(b), "l"(c));
    return d;
}
__device__ __forceinline__ u64 relu2(u64 v) {
    float a, b; upk2(v, a, b);
    a = fmaxf(a, 0.0f); b = fmaxf(b, 0.0f);
    return pk2(a, b);
}

__global__ __launch_bounds__(128)
void k_main(const float* __restrict__ x,
            const float* __restrict__ w1, const float* __restrict__ b1,
            const float* __restrict__ w2, const float* __restrict__ b2,
            const float* __restrict__ w3, const float* __restrict__ b3,
            const float* __restrict__ growth,
            float* __restrict__ out)
{
    // Weights duplicated as (w,w) f32x2 pairs; layouts chosen so every fetch
    // is a 16B ld.shared.v2.u64 feeding two fma2.
    // swr1[c][f][o]: c=input channel(8), f=feature(x,sx,sy)(3), o=output(32)
    __shared__ __align__(16) u64 swr1[8 * 3 * 32];
    __shared__ __align__(16) u64 sw2[32 * 32];   // [o][c], c contiguous
    __shared__ __align__(16) u64 sw3[8 * 32];    // [o][c], c contiguous
    __shared__ __align__(16) u64 sb1[32], sb2[32], sb3[8];
    __shared__ float s_gr;
    __shared__ float s_boostbase;

    const int tid = threadIdx.x;
    for (int i = tid; i < 8 * 32; i += 128) {
        int c = i >> 5, o = i & 31;
        float a = w1[o * 24 + c];
        float s = w1[o * 24 + 8 + c];
        float t = w1[o * 24 + 16 + c];
        swr1[c * 96 + o]      = pk2(a, a);
        swr1[c * 96 + 32 + o] = pk2(s, s);
        swr1[c * 96 + 64 + o] = pk2(t, t);
    }
    for (int i = tid; i < 32 * 32; i += 128) { float w = w2[i]; sw2[i] = pk2(w, w); }
    for (int i = tid; i < 8 * 32;  i += 128) { float w = w3[i]; sw3[i] = pk2(w, w); }
    if (tid < 32) { float v1 = b1[tid]; sb1[tid] = pk2(v1, v1);
                    float v2 = b2[tid]; sb2[tid] = pk2(v2, v2); }
    if (tid < 8)  { float v3 = b3[tid]; sb3[tid] = pk2(v3, v3); }
    if (tid == 0) {
        s_gr = growth[0];
        float ratio = (float)g_alive_count * (1.0f / (float)NPIX);
        s_boostbase = (ratio < 0.2f) ? 0.2f : 0.0f;
    }
    __syncthreads();

    // 2 horizontally adjacent pixels per thread; block = 16x8 threads -> 32x8 pixel tile
    const int tx = tid & 15, ty = tid >> 4;
    const int xi = (blockIdx.x * 16 + tx) * 2;
    const int yi = blockIdx.y * 8 + ty;
    const int b  = blockIdx.z;

    const float* xb = x + (size_t)b * (C_ * HW_);

    const bool ok_t = (yi > 0), ok_b = (yi < H_ - 1);
    const bool ok_l = (xi > 0), ok_r = (xi + 2 < W_);

    const float AT = 0.1f;
    u64 xcen[8];                 // center x values per channel (residual path)
    bool alive0 = false, alive1 = false;

    // Layer 1 accumulators, init with bias; folded incrementally per channel
    u64 h1[32];
    #pragma unroll
    for (int o = 0; o < 32; o++) h1[o] = sb1[o];

    #pragma unroll
    for (int c = 0; c < 8; c++) {
        const float* pc = xb + (size_t)c * HW_ + (size_t)yi * W_ + xi;
        float v00, v01, v02, v03, v10, v11, v12, v13, v20, v21, v22, v23;
        v00 = (ok_t && ok_l) ? __ldg(pc - W_ - 1) : 0.0f;
        v01 =  ok_t          ? __ldg(pc - W_    ) : 0.0f;
        v02 =  ok_t          ? __ldg(pc - W_ + 1) : 0.0f;
        v03 = (ok_t && ok_r) ? __ldg(pc - W_ + 2) : 0.0f;
        v10 =  ok_l          ? __ldg(pc - 1)      : 0.0f;
        v11 =                  __ldg(pc);
        v12 =                  __ldg(pc + 1);
        v13 =  ok_r          ? __ldg(pc + 2)      : 0.0f;
        v20 = (ok_b && ok_l) ? __ldg(pc + W_ - 1) : 0.0f;
        v21 =  ok_b          ? __ldg(pc + W_    ) : 0.0f;
        v22 =  ok_b          ? __ldg(pc + W_ + 1) : 0.0f;
        v23 = (ok_b && ok_r) ? __ldg(pc + W_ + 2) : 0.0f;

        float sx0 = (v02 - v00) + 2.0f * (v12 - v10) + (v22 - v20);
        float sx1 = (v03 - v01) + 2.0f * (v13 - v11) + (v23 - v21);
        float sy0 = (v20 + 2.0f * v21 + v22) - (v00 + 2.0f * v01 + v02);
        float sy1 = (v21 + 2.0f * v22 + v23) - (v01 + 2.0f * v02 + v03);

        u64 cen = pk2(v11, v12);
        u64 sxp = pk2(sx0, sx1);
        u64 syp = pk2(sy0, sy1);
        xcen[c] = cen;

        if (c == 3) {
            // growth zone: any in-bounds 3x3 neighbor alive  (k/9 > 0.01 <=> k >= 1)
            alive0 = (v00 > AT) | (v01 > AT) | (v02 > AT)
                   | (v10 > AT) | (v11 > AT) | (v12 > AT)
                   | (v20 > AT) | (v21 > AT) | (v22 > AT);
            alive1 = (v01 > AT) | (v02 > AT) | (v03 > AT)
                   | (v11 > AT) | (v12 > AT) | (v13 > AT)
                   | (v21 > AT) | (v22 > AT) | (v23 > AT);
        }

        const u64* wx = &swr1[c * 96];
        #pragma unroll
        for (int o = 0; o < 32; o += 2) {
            ulonglong2 qx = *reinterpret_cast<const ulonglong2*>(&wx[o]);
            ulonglong2 qs = *reinterpret_cast<const ulonglong2*>(&wx[32 + o]);
            ulonglong2 qt = *reinterpret_cast<const ulonglong2*>(&wx[64 + o]);
            h1[o]     = fma2(syp, qt.x, fma2(sxp, qs.x, fma2(cen, qx.x, h1[o])));
            h1[o + 1] = fma2(syp, qt.y, fma2(sxp, qs.y, fma2(cen, qx.y, h1[o + 1])));
        }
    }

    #pragma unroll
    for (int o = 0; o < 32; o++) h1[o] = relu2(h1[o]);

    // Layer 2: 32 -> 32, ReLU  (vectorized weight fetch: 2 weights per LDS.128)
    u64 h2[32];
    #pragma unroll
    for (int o = 0; o < 32; o++) {
        u64 acc = sb2[o];
        const u64* wr = &sw2[o * 32];
        #pragma unroll
        for (int c = 0; c < 32; c += 2) {
            ulonglong2 q = *reinterpret_cast<const ulonglong2*>(&wr[c]);
            acc = fma2(h1[c + 1], q.y, fma2(h1[c], q.x, acc));
        }
        h2[o] = relu2(acc);
    }

    // Layer 3: 32 -> 8, scale, boost, residual, clip, write
    const float gr = s_gr;
    const float boost0 = alive0 ? s_boostbase : 0.0f;
    const float boost1 = alive1 ? s_boostbase : 0.0f;
    float* ob = out + (size_t)b * (C_ * HW_) + (size_t)yi * W_ + xi;

    #pragma unroll
    for (int o = 0; o < 8; o++) {
        u64 acc = sb3[o];
        const u64* wr = &sw3[o * 32];
        #pragma unroll
        for (int c = 0; c < 32; c += 2) {
            ulonglong2 q = *reinterpret_cast<const ulonglong2*>(&wr[c]);
            acc = fma2(h2[c + 1], q.y, fma2(h2[c], q.x, acc));
        }
        float d0, d1; upk2(acc, d0, d1);
        d0 *= gr; d1 *= gr;
        if (o == 3) { d0 += boost0; d1 += boost1; }
        float xc0, xc1; upk2(xcen[o], xc0, xc1);
        float n0 = fminf(fmaxf(xc0 + d0, -1.0f), 1.0f);
        float n1 = fminf(fmaxf(xc1 + d1, -1.0f), 1.0f);
        if (o == 3) { n0 = fmaxf(n0, 0.0f); n1 = fmaxf(n1, 0.0f); }
        *reinterpret_cast<float2*>(ob + (size_t)o * HW_) = make_float2(n0, n1);
    }
}

extern "C" void kernel_launch(void* const* d_in, const int* in_sizes, int n_in,
                              void* d_out, int out_size)
{
    const float* x  = (const float*)d_in[0];
    const float* w1 = (const float*)d_in[1];
    const float* b1 = (const float*)d_in[2];
    const float* w2 = (const float*)d_in[3];
    const float* b2 = (const float*)d_in[4];
    const float* w3 = (const float*)d_in[5];
    const float* b3 = (const float*)d_in[6];
    const float* gr = (const float*)d_in[7];
    float* out = (float*)d_out;

    k_zero<<<1, 1>>>();
    k_count<<<4096, 256>>>(x);
    k_main<<<dim3(W_ / 32, H_ / 8, B_), 128>>>(x, w1, b1, w2, b2, w3, b3, gr, out);
}

// round 3
// speedup vs baseline: 1.5648x; 1.3788x over previous
#include <cuda_runtime.h>

typedef unsigned int u32;

#define B_   16
#define C_   8
#define H_   512
#define W_   512
#define HW_  (H_*W_)
#define NPIX (B_*HW_)

__device__ unsigned int g_alive_count;

__global__ void k_zero() { g_alive_count = 0u; }

// Count alive cells (channel 3 > 0.1) over all batches. One float4 per thread.
__global__ void k_count(const float* __restrict__ x) {
    __shared__ unsigned int s_sum;
    if (threadIdx.x == 0) s_sum = 0u;
    __syncthreads();
    unsigned int gid  = blockIdx.x * blockDim.x + threadIdx.x;
    unsigned int b    = gid >> 16;
    unsigned int off4 = gid & 65535u;
    const float4* p = reinterpret_cast<const float4*>(
        x + (size_t)b * (C_ * HW_) + (size_t)3 * HW_) + off4;
    float4 v = __ldg(p);
    unsigned int c = (v.x > 0.1f ? 1u : 0u) + (v.y > 0.1f ? 1u : 0u)
                   + (v.z > 0.1f ? 1u : 0u) + (v.w > 0.1f ? 1u : 0u);
    #pragma unroll
    for (int o = 16; o; o >>= 1) c += __shfl_down_sync(0xffffffffu, c, o);
    if ((threadIdx.x & 31) == 0) atomicAdd(&s_sum, c);
    __syncthreads();
    if (threadIdx.x == 0) atomicAdd(&g_alive_count, s_sum);
}

__device__ __forceinline__ u32 tf32c(float f) {
    u32 r; asm("cvt.rna.tf32.f32 %0, %1;" : "=r"(r) : "f"(f)); return r;
}

__device__ __forceinline__ void mma8(float* d, u32 a0, u32 a1, u32 a2, u32 a3,
                                     u32 b0, u32 b1) {
    asm volatile(
        "mma.sync.aligned.m16n8k8.row.col.f32.tf32.tf32.f32 "
        "{%0,%1,%2,%3},{%4,%5,%6,%7},{%8,%9},{%0,%1,%2,%3};"
        : "+f"(d[0]), "+f"(d[1]), "+f"(d[2]), "+f"(d[3])
        : "r"(a0), "r"(a1), "r"(a2), "r"(a3), "r"(b0), "r"(b1));
}

#define PSTR 66                 // perceived row stride (floats)
#define HSTR 34                 // hidden buffer row stride
#define PBUF (24 * PSTR)        // 1584 floats
#define HBUF (32 * HSTR)        // 1088 floats
#define WBUF (PBUF + HBUF)      // 2672 floats / warp

__global__ void __launch_bounds__(128)
k_main(const float* __restrict__ x,
       const float* __restrict__ w1, const float* __restrict__ b1,
       const float* __restrict__ w2, const float* __restrict__ b2,
       const float* __restrict__ w3, const float* __restrict__ b3,
       const float* __restrict__ growth,
       float* __restrict__ out)
{
    __shared__ float smem[4 * WBUF];   // 42.75 KB
    const int tid  = threadIdx.x;
    const int wid  = tid >> 5;
    const int lane = tid & 31;
    const int q = lane >> 2;           // groupID   (0..7)
    const int r = lane & 3;            // tid-in-group (0..3)

    float* pbuf = smem + wid * WBUF;
    float* hbuf = pbuf + PBUF;
    u32* pbu = reinterpret_cast<u32*>(pbuf);
    u32* hbu = reinterpret_cast<u32*>(hbuf);

    // ---- weights as persistent A fragments (tf32) ----
    u32 A1[2][3][4];
    #pragma unroll
    for (int mt = 0; mt < 2; mt++)
        #pragma unroll
        for (int kt = 0; kt < 3; kt++) {
            int row = 16 * mt + q, col = 8 * kt + r;
            A1[mt][kt][0] = tf32c(__ldg(&w1[row * 24 + col]));
            A1[mt][kt][1] = tf32c(__ldg(&w1[(row + 8) * 24 + col]));
            A1[mt][kt][2] = tf32c(__ldg(&w1[row * 24 + col + 4]));
            A1[mt][kt][3] = tf32c(__ldg(&w1[(row + 8) * 24 + col + 4]));
        }
    u32 A2[2][4][4];
    #pragma unroll
    for (int mt = 0; mt < 2; mt++)
        #pragma unroll
        for (int kt = 0; kt < 4; kt++) {
            int row = 16 * mt + q, col = 8 * kt + r;
            A2[mt][kt][0] = tf32c(__ldg(&w2[row * 32 + col]));
            A2[mt][kt][1] = tf32c(__ldg(&w2[(row + 8) * 32 + col]));
            A2[mt][kt][2] = tf32c(__ldg(&w2[row * 32 + col + 4]));
            A2[mt][kt][3] = tf32c(__ldg(&w2[(row + 8) * 32 + col + 4]));
        }
    u32 A3[4][2];                      // rows 8..15 of the m16 tile are zero (discarded)
    #pragma unroll
    for (int kt = 0; kt < 4; kt++) {
        A3[kt][0] = tf32c(__ldg(&w3[q * 32 + 8 * kt + r]));
        A3[kt][1] = tf32c(__ldg(&w3[q * 32 + 8 * kt + r + 4]));
    }
    const float bi1a = __ldg(&b1[q]),      bi1b = __ldg(&b1[q + 8]);
    const float bi1c = __ldg(&b1[16 + q]), bi1d = __ldg(&b1[24 + q]);
    const float bi2a = __ldg(&b2[q]),      bi2b = __ldg(&b2[q + 8]);
    const float bi2c = __ldg(&b2[16 + q]), bi2d = __ldg(&b2[24 + q]);
    const float bi3  = __ldg(&b3[q]);
    const float gr   = __ldg(&growth[0]);
    const float bbase = ((float)g_alive_count < 0.2f * (float)NPIX) ? 0.2f : 0.0f;

    // ---- strip coordinates: warp handles 64 consecutive pixels in one row ----
    const int strip = blockIdx.x * 4 + wid;     // 0..7
    const int x0 = strip * 64;
    const int yy = blockIdx.y;
    const int bz = blockIdx.z;
    const float* xb = x + (size_t)bz * (C_ * HW_);

    // ---- perceive: 2 px per lane, fp32 sobel, store tf32 to pbuf ----
    const int gx = x0 + 2 * lane;
    const bool ok_t = (yy > 0), ok_bm = (yy < H_ - 1);
    const bool ok_l = (gx > 0), ok_r = (gx + 2 < W_);
    const float AT = 0.1f;
    float boost0 = 0.0f, boost1 = 0.0f;

    #pragma unroll
    for (int c = 0; c < 8; c++) {
        const float* pc = xb + (size_t)c * HW_ + (size_t)yy * W_ + gx;
        float v00, v01, v02, v03, v10, v11, v12, v13, v20, v21, v22, v23;
        v00 = (ok_t && ok_l) ? __ldg(pc - W_ - 1) : 0.0f;
        v01 =  ok_t          ? __ldg(pc - W_    ) : 0.0f;
        v02 =  ok_t          ? __ldg(pc - W_ + 1) : 0.0f;
        v03 = (ok_t && ok_r) ? __ldg(pc - W_ + 2) : 0.0f;
        v10 =  ok_l          ? __ldg(pc - 1)      : 0.0f;
        v11 =                  __ldg(pc);
        v12 =                  __ldg(pc + 1);
        v13 =  ok_r          ? __ldg(pc + 2)      : 0.0f;
        v20 = (ok_bm && ok_l) ? __ldg(pc + W_ - 1) : 0.0f;
        v21 =  ok_bm          ? __ldg(pc + W_    ) : 0.0f;
        v22 =  ok_bm          ? __ldg(pc + W_ + 1) : 0.0f;
        v23 = (ok_bm && ok_r) ? __ldg(pc + W_ + 2) : 0.0f;

        float sx0 = (v02 - v00) + 2.0f * (v12 - v10) + (v22 - v20);
        float sx1 = (v03 - v01) + 2.0f * (v13 - v11) + (v23 - v21);
        float sy0 = (v20 + 2.0f * v21 + v22) - (v00 + 2.0f * v01 + v02);
        float sy1 = (v21 + 2.0f * v22 + v23) - (v01 + 2.0f * v02 + v03);

        *reinterpret_cast<uint2*>(&pbu[c * PSTR + 2 * lane])
            = make_uint2(tf32c(v11), tf32c(v12));
        *reinterpret_cast<uint2*>(&pbu[(8 + c) * PSTR + 2 * lane])
            = make_uint2(tf32c(sx0), tf32c(sx1));
        *reinterpret_cast<uint2*>(&pbu[(16 + c) * PSTR + 2 * lane])
            = make_uint2(tf32c(sy0), tf32c(sy1));

        if (c == 3) {
            bool a0 = (v00 > AT) | (v01 > AT) | (v02 > AT)
                    | (v10 > AT) | (v11 > AT) | (v12 > AT)
                    | (v20 > AT) | (v21 > AT) | (v22 > AT);
            bool a1 = (v01 > AT) | (v02 > AT) | (v03 > AT)
                    | (v11 > AT) | (v12 > AT) | (v13 > AT)
                    | (v21 > AT) | (v22 > AT) | (v23 > AT);
            boost0 = a0 ? bbase : 0.0f;
            boost1 = a1 ? bbase : 0.0f;
        }
    }
    __syncwarp();

    // ---- two 32-pixel GEMM chunks ----
    #pragma unroll
    for (int chunk = 0; chunk < 2; chunk++) {
        const int cb = 32 * chunk;

        // Layer 1: [32 out x 24 k] x [24 k x 32 px]
        float d[2][4][4];
        #pragma unroll
        for (int mt = 0; mt < 2; mt++) {
            float bl = mt ? bi1c : bi1a, bh = mt ? bi1d : bi1b;
            #pragma unroll
            for (int v = 0; v < 4; v++) {
                d[mt][v][0] = bl; d[mt][v][1] = bl;
                d[mt][v][2] = bh; d[mt][v][3] = bh;
            }
        }
        #pragma unroll
        for (int kt = 0; kt < 3; kt++)
            #pragma unroll
            for (int v = 0; v < 4; v++) {
                u32 f0 = pbu[(8 * kt + r) * PSTR + cb + 8 * v + q];
                u32 f1 = pbu[(8 * kt + r + 4) * PSTR + cb + 8 * v + q];
                mma8(d[0][v], A1[0][kt][0], A1[0][kt][1], A1[0][kt][2], A1[0][kt][3], f0, f1);
                mma8(d[1][v], A1[1][kt][0], A1[1][kt][1], A1[1][kt][2], A1[1][kt][3], f0, f1);
            }
        // relu + cvt + store h1
        #pragma unroll
        for (int mt = 0; mt < 2; mt++)
            #pragma unroll
            for (int v = 0; v < 4; v++) {
                int row = 16 * mt + q, px = 8 * v + 2 * r;
                *reinterpret_cast<uint2*>(&hbu[row * HSTR + px])
                    = make_uint2(tf32c(fmaxf(d[mt][v][0], 0.0f)),
                                 tf32c(fmaxf(d[mt][v][1], 0.0f)));
                *reinterpret_cast<uint2*>(&hbu[(row + 8) * HSTR + px])
                    = make_uint2(tf32c(fmaxf(d[mt][v][2], 0.0f)),
                                 tf32c(fmaxf(d[mt][v][3], 0.0f)));
            }
        __syncwarp();

        // preload ALL layer-2 B fragments (hbuf gets overwritten by h2)
        u32 Bf[4][4][2];
        #pragma unroll
        for (int kt = 0; kt < 4; kt++)
            #pragma unroll
            for (int v = 0; v < 4; v++) {
                Bf[kt][v][0] = hbu[(8 * kt + r) * HSTR + 8 * v + q];
                Bf[kt][v][1] = hbu[(8 * kt + r + 4) * HSTR + 8 * v + q];
            }
        __syncwarp();

        // Layer 2: [32 x 32] x [32 x 32 px]
        #pragma unroll
        for (int mt = 0; mt < 2; mt++) {
            float bl = mt ? bi2c : bi2a, bh = mt ? bi2d : bi2b;
            #pragma unroll
            for (int v = 0; v < 4; v++) {
                d[mt][v][0] = bl; d[mt][v][1] = bl;
                d[mt][v][2] = bh; d[mt][v][3] = bh;
            }
        }
        #pragma unroll
        for (int kt = 0; kt < 4; kt++)
            #pragma unroll
            for (int v = 0; v < 4; v++) {
                mma8(d[0][v], A2[0][kt][0], A2[0][kt][1], A2[0][kt][2], A2[0][kt][3],
                     Bf[kt][v][0], Bf[kt][v][1]);
                mma8(d[1][v], A2[1][kt][0], A2[1][kt][1], A2[1][kt][2], A2[1][kt][3],
                     Bf[kt][v][0], Bf[kt][v][1]);
            }
        // relu + cvt + store h2 (overwrite hbuf)
        #pragma unroll
        for (int mt = 0; mt < 2; mt++)
            #pragma unroll
            for (int v = 0; v < 4; v++) {
                int row = 16 * mt + q, px = 8 * v + 2 * r;
                *reinterpret_cast<uint2*>(&hbu[row * HSTR + px])
                    = make_uint2(tf32c(fmaxf(d[mt][v][0], 0.0f)),
                                 tf32c(fmaxf(d[mt][v][1], 0.0f)));
                *reinterpret_cast<uint2*>(&hbu[(row + 8) * HSTR + px])
                    = make_uint2(tf32c(fmaxf(d[mt][v][2], 0.0f)),
                                 tf32c(fmaxf(d[mt][v][3], 0.0f)));
            }
        __syncwarp();

        // Layer 3: [8(+8 pad) x 32] x [32 x 32 px]   (rows 8..15 discarded)
        float e[4][4];
        #pragma unroll
        for (int v = 0; v < 4; v++) { e[v][0] = bi3; e[v][1] = bi3; e[v][2] = 0.f; e[v][3] = 0.f; }
        #pragma unroll
        for (int kt = 0; kt < 4; kt++)
            #pragma unroll
            for (int v = 0; v < 4; v++) {
                u32 f0 = hbu[(8 * kt + r) * HSTR + 8 * v + q];
                u32 f1 = hbu[(8 * kt + r + 4) * HSTR + 8 * v + q];
                mma8(e[v], A3[kt][0], 0u, A3[kt][1], 0u, f0, f1);
            }
        __syncwarp();   // protects hbuf reads from next chunk's h1 stores

        // epilogue: dx*gr (+boost ch3), residual, clip, alpha clamp, store
        #pragma unroll
        for (int v = 0; v < 4; v++) {
            int px  = cb + 8 * v + 2 * r;        // local col (even)
            int gpx = x0 + px;
            int src = (cb >> 1) + 4 * v + r;     // lane holding boost for this px pair
            float bo0 = __shfl_sync(0xffffffffu, boost0, src);
            float bo1 = __shfl_sync(0xffffffffu, boost1, src);
            float dx0 = e[v][0] * gr;
            float dx1 = e[v][1] * gr;
            if (q == 3) { dx0 += bo0; dx1 += bo1; }
            float2 xv = __ldg(reinterpret_cast<const float2*>(
                xb + (size_t)q * HW_ + (size_t)yy * W_ + gpx));
            float n0 = fminf(fmaxf(xv.x + dx0, -1.0f), 1.0f);
            float n1 = fminf(fmaxf(xv.y + dx1, -1.0f), 1.0f);
            if (q == 3) { n0 = fmaxf(n0, 0.0f); n1 = fmaxf(n1, 0.0f); }
            *reinterpret_cast<float2*>(out + (size_t)bz * (C_ * HW_)
                + (size_t)q * HW_ + (size_t)yy * W_ + gpx) = make_float2(n0, n1);
        }
    }
}

extern "C" void kernel_launch(void* const* d_in, const int* in_sizes, int n_in,
                              void* d_out, int out_size)
{
    const float* x  = (const float*)d_in[0];
    const float* w1 = (const float*)d_in[1];
    const float* b1 = (const float*)d_in[2];
    const float* w2 = (const float*)d_in[3];
    const float* b2 = (const float*)d_in[4];
    const float* w3 = (const float*)d_in[5];
    const float* b3 = (const float*)d_in[6];
    const float* gr = (const float*)d_in[7];
    float* out = (float*)d_out;

    k_zero<<<1, 1>>>();
    k_count<<<4096, 256>>>(x);
    k_main<<<dim3(2, H_, B_), 128>>>(x, w1, b1, w2, b2, w3, b3, gr, out);
}

// round 4
// speedup vs baseline: 2.2927x; 1.4652x over previous
#include <cuda_runtime.h>
#include <cuda_fp16.h>

typedef unsigned int u32;

#define B_   16
#define C_   8
#define H_   512
#define W_   512
#define HW_  (H_*W_)
#define NPIX (B_*HW_)

__device__ unsigned int g_alive_count;

__global__ void k_zero() { g_alive_count = 0u; }

__global__ void k_count(const float* __restrict__ x) {
    __shared__ unsigned int s_sum;
    if (threadIdx.x == 0) s_sum = 0u;
    __syncthreads();
    unsigned int gid  = blockIdx.x * blockDim.x + threadIdx.x;
    unsigned int b    = gid >> 16;
    unsigned int off4 = gid & 65535u;
    const float4* p = reinterpret_cast<const float4*>(
        x + (size_t)b * (C_ * HW_) + (size_t)3 * HW_) + off4;
    float4 v = __ldg(p);
    unsigned int c = (v.x > 0.1f ? 1u : 0u) + (v.y > 0.1f ? 1u : 0u)
                   + (v.z > 0.1f ? 1u : 0u) + (v.w > 0.1f ? 1u : 0u);
    #pragma unroll
    for (int o = 16; o; o >>= 1) c += __shfl_down_sync(0xffffffffu, c, o);
    if ((threadIdx.x & 31) == 0) atomicAdd(&s_sum, c);
    __syncthreads();
    if (threadIdx.x == 0) atomicAdd(&g_alive_count, s_sum);
}

__device__ __forceinline__ u32 pkh(float lo, float hi) {
    __half2 h = __floats2half2_rn(lo, hi);
    return *reinterpret_cast<u32*>(&h);
}

__device__ __forceinline__ void mma16(float* d, const u32* a, u32 b0, u32 b1) {
    asm volatile(
        "mma.sync.aligned.m16n8k16.row.col.f32.f16.f16.f32 "
        "{%0,%1,%2,%3},{%4,%5,%6,%7},{%8,%9},{%0,%1,%2,%3};"
        : "+f"(d[0]), "+f"(d[1]), "+f"(d[2]), "+f"(d[3])
        : "r"(a[0]), "r"(a[1]), "r"(a[2]), "r"(a[3]), "r"(b0), "r"(b1));
}

// per-warp smem (halfs): pbuf 64px x 40, h1 32px x 40, h2 32px x 40
#define PB_H   (64 * 40)
#define HB_H   (32 * 40)
#define WARP_H (PB_H + 2 * HB_H)   // 5120 halfs = 10240 B

__global__ void __launch_bounds__(128)
k_main(const float* __restrict__ x,
       const float* __restrict__ w1, const float* __restrict__ b1,
       const float* __restrict__ w2, const float* __restrict__ b2,
       const float* __restrict__ w3, const float* __restrict__ b3,
       const float* __restrict__ growth,
       float* __restrict__ out)
{
    __shared__ __align__(16) __half smem[4 * WARP_H];   // 40 KB
    const int tid  = threadIdx.x;
    const int wid  = tid >> 5;
    const int lane = tid & 31;
    const int q = lane >> 2;      // 0..7
    const int r = lane & 3;       // 0..3

    __half* pb  = smem + wid * WARP_H;
    __half* h1b = pb + PB_H;
    __half* h2b = h1b + HB_H;
    u32* pb32 = reinterpret_cast<u32*>(pb);
    u32* h132 = reinterpret_cast<u32*>(h1b);
    u32* h232 = reinterpret_cast<u32*>(h2b);

    // ---- persistent A fragments (fp16), m16n8k16 layout ----
    // a0={A[q][c],A[q][c+1]} a1={A[q+8][c],..} a2={A[q][c+8],..} a3={A[q+8][c+8],..}
    u32 A1[2][2][4];
    #pragma unroll
    for (int mt = 0; mt < 2; mt++)
        #pragma unroll
        for (int kt = 0; kt < 2; kt++) {
            int m0 = 16 * mt + q, m1 = m0 + 8;
            int c0 = 16 * kt + 2 * r, c2 = c0 + 8;
            A1[mt][kt][0] = pkh(__ldg(&w1[m0 * 24 + c0]), __ldg(&w1[m0 * 24 + c0 + 1]));
            A1[mt][kt][1] = pkh(__ldg(&w1[m1 * 24 + c0]), __ldg(&w1[m1 * 24 + c0 + 1]));
            if (kt == 0) {
                A1[mt][kt][2] = pkh(__ldg(&w1[m0 * 24 + c2]), __ldg(&w1[m0 * 24 + c2 + 1]));
                A1[mt][kt][3] = pkh(__ldg(&w1[m1 * 24 + c2]), __ldg(&w1[m1 * 24 + c2 + 1]));
            } else {          // cols 24..31 are k padding -> zero
                A1[mt][kt][2] = 0u;
                A1[mt][kt][3] = 0u;
            }
        }
    u32 A2[2][2][4];
    #pragma unroll
    for (int mt = 0; mt < 2; mt++)
        #pragma unroll
        for (int kt = 0; kt < 2; kt++) {
            int m0 = 16 * mt + q, m1 = m0 + 8;
            int c0 = 16 * kt + 2 * r, c2 = c0 + 8;
            A2[mt][kt][0] = pkh(__ldg(&w2[m0 * 32 + c0]), __ldg(&w2[m0 * 32 + c0 + 1]));
            A2[mt][kt][1] = pkh(__ldg(&w2[m1 * 32 + c0]), __ldg(&w2[m1 * 32 + c0 + 1]));
            A2[mt][kt][2] = pkh(__ldg(&w2[m0 * 32 + c2]), __ldg(&w2[m0 * 32 + c2 + 1]));
            A2[mt][kt][3] = pkh(__ldg(&w2[m1 * 32 + c2]), __ldg(&w2[m1 * 32 + c2 + 1]));
        }
    u32 A3[2][4];                  // rows 8..15 zero (a1=a3=0)
    #pragma unroll
    for (int kt = 0; kt < 2; kt++) {
        int c0 = 16 * kt + 2 * r, c2 = c0 + 8;
        A3[kt][0] = pkh(__ldg(&w3[q * 32 + c0]), __ldg(&w3[q * 32 + c0 + 1]));
        A3[kt][1] = 0u;
        A3[kt][2] = pkh(__ldg(&w3[q * 32 + c2]), __ldg(&w3[q * 32 + c2 + 1]));
        A3[kt][3] = 0u;
    }
    const float bi1a = __ldg(&b1[q]),      bi1b = __ldg(&b1[q + 8]);
    const float bi1c = __ldg(&b1[16 + q]), bi1d = __ldg(&b1[24 + q]);
    const float bi2a = __ldg(&b2[q]),      bi2b = __ldg(&b2[q + 8]);
    const float bi2c = __ldg(&b2[16 + q]), bi2d = __ldg(&b2[24 + q]);
    const float bi3  = __ldg(&b3[q]);
    const float gr   = __ldg(&growth[0]);
    const float bbase = ((float)g_alive_count < 0.2f * (float)NPIX) ? 0.2f : 0.0f;

    // ---- strip coords: warp = 64 consecutive px in one row ----
    const int strip = blockIdx.x * 4 + wid;
    const int x0 = strip * 64;
    const int yy = blockIdx.y;
    const int bz = blockIdx.z;
    const float* xb = x + (size_t)bz * (C_ * HW_);

    // zero k-pad cols 24..31 (words 12..15) for this lane's two rows
    #pragma unroll
    for (int p = 0; p < 2; p++) {
        int row = 2 * lane + p;
        pb32[row * 20 + 12] = 0u; pb32[row * 20 + 13] = 0u;
        pb32[row * 20 + 14] = 0u; pb32[row * 20 + 15] = 0u;
    }

    // ---- perceive: 2 px/lane, fp32 sobel, fp16 store [px][k] ----
    const int gx = x0 + 2 * lane;
    const bool ok_t = (yy > 0), ok_bm = (yy < H_ - 1);
    const bool ok_l = (gx > 0), ok_r = (gx + 2 < W_);
    const float AT = 0.1f;
    float boost0 = 0.0f, boost1 = 0.0f;

    #pragma unroll
    for (int c = 0; c < 8; c++) {
        const float* pc = xb + (size_t)c * HW_ + (size_t)yy * W_ + gx;
        float v00, v01, v02, v03, v10, v11, v12, v13, v20, v21, v22, v23;
        v00 = (ok_t && ok_l) ? __ldg(pc - W_ - 1) : 0.0f;
        v01 =  ok_t          ? __ldg(pc - W_    ) : 0.0f;
        v02 =  ok_t          ? __ldg(pc - W_ + 1) : 0.0f;
        v03 = (ok_t && ok_r) ? __ldg(pc - W_ + 2) : 0.0f;
        v10 =  ok_l          ? __ldg(pc - 1)      : 0.0f;
        v11 =                  __ldg(pc);
        v12 =                  __ldg(pc + 1);
        v13 =  ok_r          ? __ldg(pc + 2)      : 0.0f;
        v20 = (ok_bm && ok_l) ? __ldg(pc + W_ - 1) : 0.0f;
        v21 =  ok_bm          ? __ldg(pc + W_    ) : 0.0f;
        v22 =  ok_bm          ? __ldg(pc + W_ + 1) : 0.0f;
        v23 = (ok_bm && ok_r) ? __ldg(pc + W_ + 2) : 0.0f;

        float sx0 = (v02 - v00) + 2.0f * (v12 - v10) + (v22 - v20);
        float sx1 = (v03 - v01) + 2.0f * (v13 - v11) + (v23 - v21);
        float sy0 = (v20 + 2.0f * v21 + v22) - (v00 + 2.0f * v01 + v02);
        float sy1 = (v21 + 2.0f * v22 + v23) - (v01 + 2.0f * v02 + v03);

        int r0 = (2 * lane) * 40, r1 = (2 * lane + 1) * 40;
        pb[r0 + c]      = __float2half_rn(v11);
        pb[r1 + c]      = __float2half_rn(v12);
        pb[r0 + 8 + c]  = __float2half_rn(sx0);
        pb[r1 + 8 + c]  = __float2half_rn(sx1);
        pb[r0 + 16 + c] = __float2half_rn(sy0);
        pb[r1 + 16 + c] = __float2half_rn(sy1);

        if (c == 3) {
            bool a0 = (v00 > AT) | (v01 > AT) | (v02 > AT)
                    | (v10 > AT) | (v11 > AT) | (v12 > AT)
                    | (v20 > AT) | (v21 > AT) | (v22 > AT);
            bool a1 = (v01 > AT) | (v02 > AT) | (v03 > AT)
                    | (v11 > AT) | (v12 > AT) | (v13 > AT)
                    | (v21 > AT) | (v22 > AT) | (v23 > AT);
            boost0 = a0 ? bbase : 0.0f;
            boost1 = a1 ? bbase : 0.0f;
        }
    }
    __syncwarp();

    #pragma unroll
    for (int chunk = 0; chunk < 2; chunk++) {
        const int cb = 32 * chunk;

        // ---- Layer 1 ----
        float d[2][4][4];
        #pragma unroll
        for (int mt = 0; mt < 2; mt++) {
            float bl = mt ? bi1c : bi1a, bh = mt ? bi1d : bi1b;
            #pragma unroll
            for (int v = 0; v < 4; v++) {
                d[mt][v][0] = bl; d[mt][v][1] = bl;
                d[mt][v][2] = bh; d[mt][v][3] = bh;
            }
        }
        #pragma unroll
        for (int kt = 0; kt < 2; kt++)
            #pragma unroll
            for (int v = 0; v < 4; v++) {
                int px = cb + 8 * v + q;
                u32 b0 = pb32[px * 20 + 8 * kt + r];
                u32 b1 = pb32[px * 20 + 8 * kt + r + 4];
                mma16(d[0][v], A1[0][kt], b0, b1);
                mma16(d[1][v], A1[1][kt], b0, b1);
            }
        #pragma unroll
        for (int mt = 0; mt < 2; mt++)
            #pragma unroll
            for (int v = 0; v < 4; v++) {
                int p0 = (8 * v + 2 * r) * 40, p1 = p0 + 40;
                int k0 = 16 * mt + q;
                h1b[p0 + k0]     = __float2half_rn(fmaxf(d[mt][v][0], 0.0f));
                h1b[p1 + k0]     = __float2half_rn(fmaxf(d[mt][v][1], 0.0f));
                h1b[p0 + k0 + 8] = __float2half_rn(fmaxf(d[mt][v][2], 0.0f));
                h1b[p1 + k0 + 8] = __float2half_rn(fmaxf(d[mt][v][3], 0.0f));
            }
        __syncwarp();

        // ---- Layer 2 ----
        #pragma unroll
        for (int mt = 0; mt < 2; mt++) {
            float bl = mt ? bi2c : bi2a, bh = mt ? bi2d : bi2b;
            #pragma unroll
            for (int v = 0; v < 4; v++) {
                d[mt][v][0] = bl; d[mt][v][1] = bl;
                d[mt][v][2] = bh; d[mt][v][3] = bh;
            }
        }
        #pragma unroll
        for (int kt = 0; kt < 2; kt++)
            #pragma unroll
            for (int v = 0; v < 4; v++) {
                int px = 8 * v + q;
                u32 b0 = h132[px * 20 + 8 * kt + r];
                u32 b1 = h132[px * 20 + 8 * kt + r + 4];
                mma16(d[0][v], A2[0][kt], b0, b1);
                mma16(d[1][v], A2[1][kt], b0, b1);
            }
        #pragma unroll
        for (int mt = 0; mt < 2; mt++)
            #pragma unroll
            for (int v = 0; v < 4; v++) {
                int p0 = (8 * v + 2 * r) * 40, p1 = p0 + 40;
                int k0 = 16 * mt + q;
                h2b[p0 + k0]     = __float2half_rn(fmaxf(d[mt][v][0], 0.0f));
                h2b[p1 + k0]     = __float2half_rn(fmaxf(d[mt][v][1], 0.0f));
                h2b[p0 + k0 + 8] = __float2half_rn(fmaxf(d[mt][v][2], 0.0f));
                h2b[p1 + k0 + 8] = __float2half_rn(fmaxf(d[mt][v][3], 0.0f));
            }
        __syncwarp();

        // ---- Layer 3 (rows 8..15 zero/discarded) ----
        float e[4][4];
        #pragma unroll
        for (int v = 0; v < 4; v++) { e[v][0] = bi3; e[v][1] = bi3; e[v][2] = 0.f; e[v][3] = 0.f; }
        #pragma unroll
        for (int kt = 0; kt < 2; kt++)
            #pragma unroll
            for (int v = 0; v < 4; v++) {
                int px = 8 * v + q;
                u32 b0 = h232[px * 20 + 8 * kt + r];
                u32 b1 = h232[px * 20 + 8 * kt + r + 4];
                mma16(e[v], A3[kt], b0, b1);
            }
        __syncwarp();

        // ---- epilogue ----
        #pragma unroll
        for (int v = 0; v < 4; v++) {
            int px  = cb + 8 * v + 2 * r;
            int gpx = x0 + px;
            int src = (cb >> 1) + 4 * v + r;
            float bo0 = __shfl_sync(0xffffffffu, boost0, src);
            float bo1 = __shfl_sync(0xffffffffu, boost1, src);
            float dx0 = e[v][0] * gr;
            float dx1 = e[v][1] * gr;
            if (q == 3) { dx0 += bo0; dx1 += bo1; }
            float2 xv = __ldg(reinterpret_cast<const float2*>(
                xb + (size_t)q * HW_ + (size_t)yy * W_ + gpx));
            float n0 = fminf(fmaxf(xv.x + dx0, -1.0f), 1.0f);
            float n1 = fminf(fmaxf(xv.y + dx1, -1.0f), 1.0f);
            if (q == 3) { n0 = fmaxf(n0, 0.0f); n1 = fmaxf(n1, 0.0f); }
            *reinterpret_cast<float2*>(out + (size_t)bz * (C_ * HW_)
                + (size_t)q * HW_ + (size_t)yy * W_ + gpx) = make_float2(n0, n1);
        }
    }
}

extern "C" void kernel_launch(void* const* d_in, const int* in_sizes, int n_in,
                              void* d_out, int out_size)
{
    const float* x  = (const float*)d_in[0];
    const float* w1 = (const float*)d_in[1];
    const float* b1 = (const float*)d_in[2];
    const float* w2 = (const float*)d_in[3];
    const float* b2 = (const float*)d_in[4];
    const float* w3 = (const float*)d_in[5];
    const float* b3 = (const float*)d_in[6];
    const float* gr = (const float*)d_in[7];
    float* out = (float*)d_out;

    k_zero<<<1, 1>>>();
    k_count<<<4096, 256>>>(x);
    k_main<<<dim3(2, H_, B_), 128>>>(x, w1, b1, w2, b2, w3, b3, gr, out);
}

// round 5
// speedup vs baseline: 2.7745x; 1.2101x over previous
#include <cuda_runtime.h>
#include <cuda_fp16.h>

typedef unsigned int u32;

#define B_   16
#define C_   8
#define H_   512
#define W_   512
#define HW_  (H_*W_)
#define NPIX (B_*HW_)

__device__ unsigned int g_alive_count;

__global__ void k_zero() { g_alive_count = 0u; }

__global__ void k_count(const float* __restrict__ x) {
    __shared__ unsigned int s_sum;
    if (threadIdx.x == 0) s_sum = 0u;
    __syncthreads();
    unsigned int gid  = blockIdx.x * blockDim.x + threadIdx.x;
    unsigned int b    = gid >> 16;
    unsigned int off4 = gid & 65535u;
    const float4* p = reinterpret_cast<const float4*>(
        x + (size_t)b * (C_ * HW_) + (size_t)3 * HW_) + off4;
    float4 v = __ldg(p);
    unsigned int c = (v.x > 0.1f ? 1u : 0u) + (v.y > 0.1f ? 1u : 0u)
                   + (v.z > 0.1f ? 1u : 0u) + (v.w > 0.1f ? 1u : 0u);
    #pragma unroll
    for (int o = 16; o; o >>= 1) c += __shfl_down_sync(0xffffffffu, c, o);
    if ((threadIdx.x & 31) == 0) atomicAdd(&s_sum, c);
    __syncthreads();
    if (threadIdx.x == 0) atomicAdd(&g_alive_count, s_sum);
}

__device__ __forceinline__ u32 pkh(float lo, float hi) {
    __half2 h = __floats2half2_rn(lo, hi);
    return *reinterpret_cast<u32*>(&h);
}

// M=pixels, N=outputs: A = activations (LDS), B = weights (persistent regs)
__device__ __forceinline__ void mma16(float* d, u32 a0, u32 a1, u32 a2, u32 a3,
                                      u32 b0, u32 b1) {
    asm volatile(
        "mma.sync.aligned.m16n8k16.row.col.f32.f16.f16.f32 "
        "{%0,%1,%2,%3},{%4,%5,%6,%7},{%8,%9},{%0,%1,%2,%3};"
        : "+f"(d[0]), "+f"(d[1]), "+f"(d[2]), "+f"(d[3])
        : "r"(a0), "r"(a1), "r"(a2), "r"(a3), "r"(b0), "r"(b1));
}

// warp buffer: 128 px rows x 20 u32 words; swizzle keeps stores & loads conflict-free
__device__ __forceinline__ int swz(int px, int w) {
    return px * 20 + (w ^ ((px >> 3) & 15));
}

// load one row window: float4 + left/right halo via shfl (+ edge scalar fixups)
__device__ __forceinline__ void loadrow(const float* p, bool okRow, bool okL, bool okR,
                                        int lane, float4& v, float& l, float& r) {
    v = okRow ? __ldg(reinterpret_cast<const float4*>(p)) : make_float4(0.f, 0.f, 0.f, 0.f);
    l = __shfl_up_sync(0xffffffffu, v.w, 1);
    r = __shfl_down_sync(0xffffffffu, v.x, 1);
    if (lane == 0)  l = (okRow && okL) ? __ldg(p - 1) : 0.0f;
    if (lane == 31) r = (okRow && okR) ? __ldg(p + 4) : 0.0f;
}

__global__ void __launch_bounds__(128)
k_main(const float* __restrict__ x,
       const float* __restrict__ w1, const float* __restrict__ b1,
       const float* __restrict__ w2, const float* __restrict__ b2,
       const float* __restrict__ w3, const float* __restrict__ b3,
       const float* __restrict__ growth,
       float* __restrict__ out)
{
    __shared__ __align__(16) u32 sbuf[4 * 128 * 20];   // 40 KB
    const int tid  = threadIdx.x;
    const int wid  = tid >> 5;
    const int lane = tid & 31;
    const int q = lane >> 2;      // 0..7
    const int r = lane & 3;       // 0..3
    u32* bw = sbuf + wid * (128 * 20);

    // ---- persistent weight B-fragments ----
    // b0 = {W[8nt+q][16kt+2r], +1},  b1 = {W[8nt+q][16kt+2r+8], +1}
    u32 W1f[4][2][2];
    #pragma unroll
    for (int nt = 0; nt < 4; nt++)
        #pragma unroll
        for (int kt = 0; kt < 2; kt++) {
            const float* wr = w1 + (8 * nt + q) * 24;
            int k0 = 16 * kt + 2 * r;
            W1f[nt][kt][0] = pkh(__ldg(&wr[k0]), __ldg(&wr[k0 + 1]));
            W1f[nt][kt][1] = (kt == 0)
                ? pkh(__ldg(&wr[k0 + 8]), __ldg(&wr[k0 + 9])) : 0u;   // k 24..31 pad
        }
    u32 W2f[4][2][2];
    #pragma unroll
    for (int nt = 0; nt < 4; nt++)
        #pragma unroll
        for (int kt = 0; kt < 2; kt++) {
            const float* wr = w2 + (8 * nt + q) * 32;
            int k0 = 16 * kt + 2 * r;
            W2f[nt][kt][0] = pkh(__ldg(&wr[k0]), __ldg(&wr[k0 + 1]));
            W2f[nt][kt][1] = pkh(__ldg(&wr[k0 + 8]), __ldg(&wr[k0 + 9]));
        }
    u32 W3f[2][2];
    #pragma unroll
    for (int kt = 0; kt < 2; kt++) {
        const float* wr = w3 + q * 32;
        int k0 = 16 * kt + 2 * r;
        W3f[kt][0] = pkh(__ldg(&wr[k0]), __ldg(&wr[k0 + 1]));
        W3f[kt][1] = pkh(__ldg(&wr[k0 + 8]), __ldg(&wr[k0 + 9]));
    }
    float bA1[4], bB1[4], bA2[4], bB2[4];
    #pragma unroll
    for (int nt = 0; nt < 4; nt++) {
        bA1[nt] = __ldg(&b1[8 * nt + 2 * r]); bB1[nt] = __ldg(&b1[8 * nt + 2 * r + 1]);
        bA2[nt] = __ldg(&b2[8 * nt + 2 * r]); bB2[nt] = __ldg(&b2[8 * nt + 2 * r + 1]);
    }
    const float bA3 = __ldg(&b3[2 * r]), bB3 = __ldg(&b3[2 * r + 1]);
    const float gr  = __ldg(&growth[0]);
    const float bbase = ((float)g_alive_count < 0.2f * (float)NPIX) ? 0.2f : 0.0f;

    // ---- coords: warp = 128 consecutive px in one row ----
    const int x0 = wid * 128;
    const int yy = blockIdx.x;
    const int bz = blockIdx.y;
    const float* xb = x + (size_t)bz * (C_ * HW_);

    const bool okT = (yy > 0), okB = (yy < H_ - 1);
    const bool okL = (x0 > 0), okR = (x0 + 128 < W_);
    const float AT = 0.1f;

    // zero k-pad words 12..15 for this lane's 4 px rows
    #pragma unroll
    for (int i = 0; i < 4; i++) {
        int px = 4 * lane + i;
        bw[swz(px, 12)] = 0u; bw[swz(px, 13)] = 0u;
        bw[swz(px, 14)] = 0u; bw[swz(px, 15)] = 0u;
    }

    // ---- perceive: channel pairs, float4 + shfl halos, 4 px/lane ----
    u32 bm0 = 0, bm1 = 0, bm2 = 0, bm3 = 0;   // boost ballots
    #pragma unroll
    for (int p = 0; p < 4; p++) {
        float m0v[4], sx0[4], sy0[4];
        float m1v[4], sx1[4], sy1[4];
        bool alive_px[4] = {false, false, false, false};
        #pragma unroll
        for (int sub = 0; sub < 2; sub++) {
            const int ch = 2 * p + sub;
            const float* base = xb + (size_t)ch * HW_ + (size_t)yy * W_ + x0 + 4 * lane;
            float4 t, m, b; float tl, tr, ml, mr, bl, br;
            loadrow(base - W_, okT,  okL, okR, lane, t, tl, tr);
            loadrow(base,      true, okL, okR, lane, m, ml, mr);
            loadrow(base + W_, okB,  okL, okR, lane, b, bl, br);

            float nt[6] = {tl, t.x, t.y, t.z, t.w, tr};
            float nm[6] = {ml, m.x, m.y, m.z, m.w, mr};
            float nb[6] = {bl, b.x, b.y, b.z, b.w, br};

            float* mv = sub ? m1v : m0v;
            float* sx = sub ? sx1 : sx0;
            float* sy = sub ? sy1 : sy0;
            #pragma unroll
            for (int i = 0; i < 4; i++) {
                mv[i] = nm[i + 1];
                sx[i] = (nt[i + 2] - nt[i]) + 2.0f * (nm[i + 2] - nm[i])
                      + (nb[i + 2] - nb[i]);
                sy[i] = (nb[i] + 2.0f * nb[i + 1] + nb[i + 2])
                      - (nt[i] + 2.0f * nt[i + 1] + nt[i + 2]);
            }
            if (p == 1 && sub == 1) {   // channel 3: 3x3 any-alive
                bool a[6];
                #pragma unroll
                for (int j = 0; j < 6; j++)
                    a[j] = (nt[j] > AT) | (nm[j] > AT) | (nb[j] > AT);
                #pragma unroll
                for (int i = 0; i < 4; i++)
                    alive_px[i] = a[i] | a[i + 1] | a[i + 2];
            }
        }
        #pragma unroll
        for (int i = 0; i < 4; i++) {
            int px = 4 * lane + i;
            bw[swz(px, p)]     = pkh(m0v[i], m1v[i]);
            bw[swz(px, 4 + p)] = pkh(sx0[i], sx1[i]);
            bw[swz(px, 8 + p)] = pkh(sy0[i], sy1[i]);
        }
        if (p == 1) {
            bm0 = __ballot_sync(0xffffffffu, alive_px[0]);
            bm1 = __ballot_sync(0xffffffffu, alive_px[1]);
            bm2 = __ballot_sync(0xffffffffu, alive_px[2]);
            bm3 = __ballot_sync(0xffffffffu, alive_px[3]);
        }
    }
    __syncwarp();

    const u32 bmsel = (q & 2) ? ((q & 1) ? bm3 : bm2) : ((q & 1) ? bm1 : bm0);

    // ---- 4 chunks of 32 px ----
    #pragma unroll
    for (int cidx = 0; cidx < 4; cidx++) {
        const int P = 32 * cidx;

        // Layer 1: [32px x 24k] x W1 -> h1[32px x 32]
        float d[2][4][4];
        #pragma unroll
        for (int mt = 0; mt < 2; mt++)
            #pragma unroll
            for (int nt = 0; nt < 4; nt++) {
                d[mt][nt][0] = bA1[nt]; d[mt][nt][1] = bB1[nt];
                d[mt][nt][2] = bA1[nt]; d[mt][nt][3] = bB1[nt];
            }
        #pragma unroll
        for (int kt = 0; kt < 2; kt++)
            #pragma unroll
            for (int mt = 0; mt < 2; mt++) {
                int px = P + 16 * mt + q;
                u32 a0 = bw[swz(px,     8 * kt + r)];
                u32 a1 = bw[swz(px + 8, 8 * kt + r)];
                u32 a2 = bw[swz(px,     8 * kt + r + 4)];
                u32 a3 = bw[swz(px + 8, 8 * kt + r + 4)];
                #pragma unroll
                for (int nt = 0; nt < 4; nt++)
                    mma16(d[mt][nt], a0, a1, a2, a3, W1f[nt][kt][0], W1f[nt][kt][1]);
            }
        __syncwarp();
        #pragma unroll
        for (int mt = 0; mt < 2; mt++)
            #pragma unroll
            for (int nt = 0; nt < 4; nt++) {
                int px = P + 16 * mt + q;
                bw[swz(px,     4 * nt + r)] = pkh(fmaxf(d[mt][nt][0], 0.f),
                                                  fmaxf(d[mt][nt][1], 0.f));
                bw[swz(px + 8, 4 * nt + r)] = pkh(fmaxf(d[mt][nt][2], 0.f),
                                                  fmaxf(d[mt][nt][3], 0.f));
            }
        __syncwarp();

        // Layer 2: h1 x W2 -> h2 (overwrite same region)
        #pragma unroll
        for (int mt = 0; mt < 2; mt++)
            #pragma unroll
            for (int nt = 0; nt < 4; nt++) {
                d[mt][nt][0] = bA2[nt]; d[mt][nt][1] = bB2[nt];
                d[mt][nt][2] = bA2[nt]; d[mt][nt][3] = bB2[nt];
            }
        #pragma unroll
        for (int kt = 0; kt < 2; kt++)
            #pragma unroll
            for (int mt = 0; mt < 2; mt++) {
                int px = P + 16 * mt + q;
                u32 a0 = bw[swz(px,     8 * kt + r)];
                u32 a1 = bw[swz(px + 8, 8 * kt + r)];
                u32 a2 = bw[swz(px,     8 * kt + r + 4)];
                u32 a3 = bw[swz(px + 8, 8 * kt + r + 4)];
                #pragma unroll
                for (int nt = 0; nt < 4; nt++)
                    mma16(d[mt][nt], a0, a1, a2, a3, W2f[nt][kt][0], W2f[nt][kt][1]);
            }
        __syncwarp();
        #pragma unroll
        for (int mt = 0; mt < 2; mt++)
            #pragma unroll
            for (int nt = 0; nt < 4; nt++) {
                int px = P + 16 * mt + q;
                bw[swz(px,     4 * nt + r)] = pkh(fmaxf(d[mt][nt][0], 0.f),
                                                  fmaxf(d[mt][nt][1], 0.f));
                bw[swz(px + 8, 4 * nt + r)] = pkh(fmaxf(d[mt][nt][2], 0.f),
                                                  fmaxf(d[mt][nt][3], 0.f));
            }
        __syncwarp();

        // Layer 3: h2 x W3 -> dx[32px x 8]
        float e[2][4];
        #pragma unroll
        for (int mt = 0; mt < 2; mt++) {
            e[mt][0] = bA3; e[mt][1] = bB3; e[mt][2] = bA3; e[mt][3] = bB3;
        }
        #pragma unroll
        for (int kt = 0; kt < 2; kt++)
            #pragma unroll
            for (int mt = 0; mt < 2; mt++) {
                int px = P + 16 * mt + q;
                u32 a0 = bw[swz(px,     8 * kt + r)];
                u32 a1 = bw[swz(px + 8, 8 * kt + r)];
                u32 a2 = bw[swz(px,     8 * kt + r + 4)];
                u32 a3 = bw[swz(px + 8, 8 * kt + r + 4)];
                mma16(e[mt], a0, a1, a2, a3, W3f[kt][0], W3f[kt][1]);
            }

        // epilogue: lane(q,r) holds px {P+16mt+q, +8} x ch {2r, 2r+1}
        #pragma unroll
        for (int mt = 0; mt < 2; mt++)
            #pragma unroll
            for (int h = 0; h < 2; h++) {
                float e0 = e[mt][2 * h], e1 = e[mt][2 * h + 1];
                int pxl = P + 16 * mt + 8 * h + q;
                int g   = x0 + pxl;
                float dx0 = e0 * gr, dx1 = e1 * gr;
                if (r == 1) {
                    float bo = ((bmsel >> (pxl >> 2)) & 1u) ? bbase : 0.0f;
                    dx1 += bo;
                }
                const float* xp = xb + (size_t)(2 * r) * HW_ + (size_t)yy * W_ + g;
                float xv0 = __ldg(xp);
                float xv1 = __ldg(xp + HW_);
                float n0 = fminf(fmaxf(xv0 + dx0, -1.0f), 1.0f);
                float n1 = fminf(fmaxf(xv1 + dx1, -1.0f), 1.0f);
                if (r == 1) n1 = fmaxf(n1, 0.0f);
                float* op = out + (size_t)bz * (C_ * HW_)
                          + (size_t)(2 * r) * HW_ + (size_t)yy * W_ + g;
                op[0]   = n0;
                op[HW_] = n1;
            }
        __syncwarp();
    }
}

extern "C" void kernel_launch(void* const* d_in, const int* in_sizes, int n_in,
                              void* d_out, int out_size)
{
    const float* x  = (const float*)d_in[0];
    const float* w1 = (const float*)d_in[1];
    const float* b1 = (const float*)d_in[2];
    const float* w2 = (const float*)d_in[3];
    const float* b2 = (const float*)d_in[4];
    const float* w3 = (const float*)d_in[5];
    const float* b3 = (const float*)d_in[6];
    const float* gr = (const float*)d_in[7];
    float* out = (float*)d_out;

    k_zero<<<1, 1>>>();
    k_count<<<4096, 256>>>(x);
    k_main<<<dim3(H_, B_), 128>>>(x, w1, b1, w2, b2, w3, b3, gr, out);
}

// round 6
// speedup vs baseline: 3.4325x; 1.2372x over previous
#include <cuda_runtime.h>
#include <cuda_fp16.h>

typedef unsigned int u32;

#define B_    16
#define C_    8
#define H_    512
#define W_    512
#define HW_   (H_*W_)
#define NPIX  (B_*HW_)
#define PGRID 592          // 4 CTAs x 148 SMs, all co-resident
#define NTILE (B_*H_)      // 8192 row-tiles

__device__ u32 g_cnt;      // alive count   (zero at call entry, reset at exit)
__device__ u32 g_arr;      // arrivals
__device__ u32 g_dep;      // departures

__device__ __forceinline__ u32 pkh(float lo, float hi) {
    __half2 h = __floats2half2_rn(lo, hi);
    return *reinterpret_cast<u32*>(&h);
}

// M=pixels, N=outputs: A = activations (LDS), B = weights (persistent regs)
__device__ __forceinline__ void mma16(float* d, u32 a0, u32 a1, u32 a2, u32 a3,
                                      u32 b0, u32 b1) {
    asm volatile(
        "mma.sync.aligned.m16n8k16.row.col.f32.f16.f16.f32 "
        "{%0,%1,%2,%3},{%4,%5,%6,%7},{%8,%9},{%0,%1,%2,%3};"
        : "+f"(d[0]), "+f"(d[1]), "+f"(d[2]), "+f"(d[3])
        : "r"(a0), "r"(a1), "r"(a2), "r"(a3), "r"(b0), "r"(b1));
}

__device__ __forceinline__ int swz(int px, int w) {
    return px * 20 + (w ^ ((px >> 3) & 15));
}

__device__ __forceinline__ void loadrow(const float* p, bool okRow, bool okL, bool okR,
                                        int lane, float4& v, float& l, float& r) {
    v = okRow ? __ldg(reinterpret_cast<const float4*>(p)) : make_float4(0.f, 0.f, 0.f, 0.f);
    l = __shfl_up_sync(0xffffffffu, v.w, 1);
    r = __shfl_down_sync(0xffffffffu, v.x, 1);
    if (lane == 0)  l = (okRow && okL) ? __ldg(p - 1) : 0.0f;
    if (lane == 31) r = (okRow && okR) ? __ldg(p + 4) : 0.0f;
}

__global__ void __launch_bounds__(128, 4)
k_main(const float* __restrict__ x,
       const float* __restrict__ w1, const float* __restrict__ b1,
       const float* __restrict__ w2, const float* __restrict__ b2,
       const float* __restrict__ w3, const float* __restrict__ b3,
       const float* __restrict__ growth,
       float* __restrict__ out)
{
    __shared__ __align__(16) u32 sbuf[4 * 128 * 20];   // 40 KB
    __shared__ u32 s_part;
    __shared__ float s_bbase;

    const int tid  = threadIdx.x;
    const int wid  = tid >> 5;
    const int lane = tid & 31;
    const int q = lane >> 2;
    const int r = lane & 3;
    u32* bw = sbuf + wid * (128 * 20);

    // ================= Phase A: global alive count =================
    if (tid == 0) s_part = 0u;
    __syncthreads();
    {
        const float4* ap = reinterpret_cast<const float4*>(x);  // view as float4
        // alpha plane of batch b is at word offset b*C*HW + 3*HW; iterate per batch
        u32 cnt = 0;
        for (int b = 0; b < B_; b++) {
            const float4* p = reinterpret_cast<const float4*>(
                x + (size_t)b * (C_ * HW_) + (size_t)3 * HW_);
            for (int i = blockIdx.x * 128 + tid; i < HW_ / 4; i += PGRID * 128) {
                float4 v = __ldg(p + i);
                cnt += (v.x > 0.1f) + (v.y > 0.1f) + (v.z > 0.1f) + (v.w > 0.1f);
            }
        }
        (void)ap;
        #pragma unroll
        for (int o = 16; o; o >>= 1) cnt += __shfl_down_sync(0xffffffffu, cnt, o);
        if (lane == 0) atomicAdd(&s_part, cnt);
    }
    __syncthreads();
    if (tid == 0) {
        atomicAdd(&g_cnt, s_part);
        __threadfence();
        atomicAdd(&g_arr, 1u);
    }
    // spin until all CTAs arrived
    {
        volatile u32* va = &g_arr;
        while (*va < PGRID) __nanosleep(128);
    }
    __threadfence();
    if (tid == 0) {
        u32 total = *((volatile u32*)&g_cnt);
        s_bbase = ((float)total < 0.2f * (float)NPIX) ? 0.2f : 0.0f;
    }
    __syncthreads();                 // whole CTA past spin & bbase ready
    const float bbase = s_bbase;
    if (tid == 0) {
        u32 d = atomicAdd(&g_dep, 1u);
        if (d == PGRID - 1) {        // last CTA out: restore zeros for next call
            g_cnt = 0u; g_arr = 0u; g_dep = 0u;
            __threadfence();
        }
    }

    // ================= persistent weight fragments (once) =================
    u32 W1f[4][2][2];
    #pragma unroll
    for (int nt = 0; nt < 4; nt++)
        #pragma unroll
        for (int kt = 0; kt < 2; kt++) {
            const float* wr = w1 + (8 * nt + q) * 24;
            int k0 = 16 * kt + 2 * r;
            W1f[nt][kt][0] = pkh(__ldg(&wr[k0]), __ldg(&wr[k0 + 1]));
            W1f[nt][kt][1] = (kt == 0)
                ? pkh(__ldg(&wr[k0 + 8]), __ldg(&wr[k0 + 9])) : 0u;
        }
    u32 W2f[4][2][2];
    #pragma unroll
    for (int nt = 0; nt < 4; nt++)
        #pragma unroll
        for (int kt = 0; kt < 2; kt++) {
            const float* wr = w2 + (8 * nt + q) * 32;
            int k0 = 16 * kt + 2 * r;
            W2f[nt][kt][0] = pkh(__ldg(&wr[k0]), __ldg(&wr[k0 + 1]));
            W2f[nt][kt][1] = pkh(__ldg(&wr[k0 + 8]), __ldg(&wr[k0 + 9]));
        }
    u32 W3f[2][2];
    #pragma unroll
    for (int kt = 0; kt < 2; kt++) {
        const float* wr = w3 + q * 32;
        int k0 = 16 * kt + 2 * r;
        W3f[kt][0] = pkh(__ldg(&wr[k0]), __ldg(&wr[k0 + 1]));
        W3f[kt][1] = pkh(__ldg(&wr[k0 + 8]), __ldg(&wr[k0 + 9]));
    }
    float bA1[4], bB1[4], bA2[4], bB2[4];
    #pragma unroll
    for (int nt = 0; nt < 4; nt++) {
        bA1[nt] = __ldg(&b1[8 * nt + 2 * r]); bB1[nt] = __ldg(&b1[8 * nt + 2 * r + 1]);
        bA2[nt] = __ldg(&b2[8 * nt + 2 * r]); bB2[nt] = __ldg(&b2[8 * nt + 2 * r + 1]);
    }
    const float bA3 = __ldg(&b3[2 * r]), bB3 = __ldg(&b3[2 * r + 1]);
    const float gr  = __ldg(&growth[0]);
    const float AT  = 0.1f;

    // ================= Phase B: persistent tile loop =================
    for (int t = blockIdx.x; t < NTILE; t += PGRID) {
        const int yy = t & (H_ - 1);
        const int bz = t >> 9;
        const int x0 = wid * 128;
        const float* xb = x + (size_t)bz * (C_ * HW_);

        const bool okT = (yy > 0), okB = (yy < H_ - 1);
        const bool okL = (x0 > 0), okR = (x0 + 128 < W_);

        // re-zero k-pad words 12..15 (h-stores clobbered them last tile)
        #pragma unroll
        for (int i = 0; i < 4; i++) {
            int px = 4 * lane + i;
            bw[swz(px, 12)] = 0u; bw[swz(px, 13)] = 0u;
            bw[swz(px, 14)] = 0u; bw[swz(px, 15)] = 0u;
        }

        // ---- perceive ----
        u32 bm0 = 0, bm1 = 0, bm2 = 0, bm3 = 0;
        #pragma unroll
        for (int p = 0; p < 4; p++) {
            float m0v[4], sx0[4], sy0[4];
            float m1v[4], sx1[4], sy1[4];
            bool alive_px[4] = {false, false, false, false};
            #pragma unroll
            for (int sub = 0; sub < 2; sub++) {
                const int ch = 2 * p + sub;
                const float* base = xb + (size_t)ch * HW_ + (size_t)yy * W_ + x0 + 4 * lane;
                float4 tt, mm, bb; float tl, tr, ml, mr, bl, br;
                loadrow(base - W_, okT,  okL, okR, lane, tt, tl, tr);
                loadrow(base,      true, okL, okR, lane, mm, ml, mr);
                loadrow(base + W_, okB,  okL, okR, lane, bb, bl, br);

                float nt_[6] = {tl, tt.x, tt.y, tt.z, tt.w, tr};
                float nm_[6] = {ml, mm.x, mm.y, mm.z, mm.w, mr};
                float nb_[6] = {bl, bb.x, bb.y, bb.z, bb.w, br};

                float* mv = sub ? m1v : m0v;
                float* sx = sub ? sx1 : sx0;
                float* sy = sub ? sy1 : sy0;
                #pragma unroll
                for (int i = 0; i < 4; i++) {
                    mv[i] = nm_[i + 1];
                    sx[i] = (nt_[i + 2] - nt_[i]) + 2.0f * (nm_[i + 2] - nm_[i])
                          + (nb_[i + 2] - nb_[i]);
                    sy[i] = (nb_[i] + 2.0f * nb_[i + 1] + nb_[i + 2])
                          - (nt_[i] + 2.0f * nt_[i + 1] + nt_[i + 2]);
                }
                if (p == 1 && sub == 1) {
                    bool a[6];
                    #pragma unroll
                    for (int j = 0; j < 6; j++)
                        a[j] = (nt_[j] > AT) | (nm_[j] > AT) | (nb_[j] > AT);
                    #pragma unroll
                    for (int i = 0; i < 4; i++)
                        alive_px[i] = a[i] | a[i + 1] | a[i + 2];
                }
            }
            #pragma unroll
            for (int i = 0; i < 4; i++) {
                int px = 4 * lane + i;
                bw[swz(px, p)]     = pkh(m0v[i], m1v[i]);
                bw[swz(px, 4 + p)] = pkh(sx0[i], sx1[i]);
                bw[swz(px, 8 + p)] = pkh(sy0[i], sy1[i]);
            }
            if (p == 1) {
                bm0 = __ballot_sync(0xffffffffu, alive_px[0]);
                bm1 = __ballot_sync(0xffffffffu, alive_px[1]);
                bm2 = __ballot_sync(0xffffffffu, alive_px[2]);
                bm3 = __ballot_sync(0xffffffffu, alive_px[3]);
            }
        }
        __syncwarp();

        const u32 bmsel = (q & 2) ? ((q & 1) ? bm3 : bm2) : ((q & 1) ? bm1 : bm0);

        // ---- 4 chunks of 32 px ----
        #pragma unroll
        for (int cidx = 0; cidx < 4; cidx++) {
            const int P = 32 * cidx;

            float d[2][4][4];
            #pragma unroll
            for (int mt = 0; mt < 2; mt++)
                #pragma unroll
                for (int nt = 0; nt < 4; nt++) {
                    d[mt][nt][0] = bA1[nt]; d[mt][nt][1] = bB1[nt];
                    d[mt][nt][2] = bA1[nt]; d[mt][nt][3] = bB1[nt];
                }
            #pragma unroll
            for (int kt = 0; kt < 2; kt++)
                #pragma unroll
                for (int mt = 0; mt < 2; mt++) {
                    int px = P + 16 * mt + q;
                    u32 a0 = bw[swz(px,     8 * kt + r)];
                    u32 a1 = bw[swz(px + 8, 8 * kt + r)];
                    u32 a2 = bw[swz(px,     8 * kt + r + 4)];
                    u32 a3 = bw[swz(px + 8, 8 * kt + r + 4)];
                    #pragma unroll
                    for (int nt = 0; nt < 4; nt++)
                        mma16(d[mt][nt], a0, a1, a2, a3, W1f[nt][kt][0], W1f[nt][kt][1]);
                }
            __syncwarp();
            #pragma unroll
            for (int mt = 0; mt < 2; mt++)
                #pragma unroll
                for (int nt = 0; nt < 4; nt++) {
                    int px = P + 16 * mt + q;
                    bw[swz(px,     4 * nt + r)] = pkh(fmaxf(d[mt][nt][0], 0.f),
                                                      fmaxf(d[mt][nt][1], 0.f));
                    bw[swz(px + 8, 4 * nt + r)] = pkh(fmaxf(d[mt][nt][2], 0.f),
                                                      fmaxf(d[mt][nt][3], 0.f));
                }
            __syncwarp();

            #pragma unroll
            for (int mt = 0; mt < 2; mt++)
                #pragma unroll
                for (int nt = 0; nt < 4; nt++) {
                    d[mt][nt][0] = bA2[nt]; d[mt][nt][1] = bB2[nt];
                    d[mt][nt][2] = bA2[nt]; d[mt][nt][3] = bB2[nt];
                }
            #pragma unroll
            for (int kt = 0; kt < 2; kt++)
                #pragma unroll
                for (int mt = 0; mt < 2; mt++) {
                    int px = P + 16 * mt + q;
                    u32 a0 = bw[swz(px,     8 * kt + r)];
                    u32 a1 = bw[swz(px + 8, 8 * kt + r)];
                    u32 a2 = bw[swz(px,     8 * kt + r + 4)];
                    u32 a3 = bw[swz(px + 8, 8 * kt + r + 4)];
                    #pragma unroll
                    for (int nt = 0; nt < 4; nt++)
                        mma16(d[mt][nt], a0, a1, a2, a3, W2f[nt][kt][0], W2f[nt][kt][1]);
                }
            __syncwarp();
            #pragma unroll
            for (int mt = 0; mt < 2; mt++)
                #pragma unroll
                for (int nt = 0; nt < 4; nt++) {
                    int px = P + 16 * mt + q;
                    bw[swz(px,     4 * nt + r)] = pkh(fmaxf(d[mt][nt][0], 0.f),
                                                      fmaxf(d[mt][nt][1], 0.f));
                    bw[swz(px + 8, 4 * nt + r)] = pkh(fmaxf(d[mt][nt][2], 0.f),
                                                      fmaxf(d[mt][nt][3], 0.f));
                }
            __syncwarp();

            float e[2][4];
            #pragma unroll
            for (int mt = 0; mt < 2; mt++) {
                e[mt][0] = bA3; e[mt][1] = bB3; e[mt][2] = bA3; e[mt][3] = bB3;
            }
            #pragma unroll
            for (int kt = 0; kt < 2; kt++)
                #pragma unroll
                for (int mt = 0; mt < 2; mt++) {
                    int px = P + 16 * mt + q;
                    u32 a0 = bw[swz(px,     8 * kt + r)];
                    u32 a1 = bw[swz(px + 8, 8 * kt + r)];
                    u32 a2 = bw[swz(px,     8 * kt + r + 4)];
                    u32 a3 = bw[swz(px + 8, 8 * kt + r + 4)];
                    mma16(e[mt], a0, a1, a2, a3, W3f[kt][0], W3f[kt][1]);
                }

            #pragma unroll
            for (int mt = 0; mt < 2; mt++)
                #pragma unroll
                for (int h = 0; h < 2; h++) {
                    float e0 = e[mt][2 * h], e1 = e[mt][2 * h + 1];
                    int pxl = P + 16 * mt + 8 * h + q;
                    int g   = x0 + pxl;
                    float dx0 = e0 * gr, dx1 = e1 * gr;
                    if (r == 1) {
                        float bo = ((bmsel >> (pxl >> 2)) & 1u) ? bbase : 0.0f;
                        dx1 += bo;
                    }
                    const float* xp = xb + (size_t)(2 * r) * HW_ + (size_t)yy * W_ + g;
                    float xv0 = __ldg(xp);
                    float xv1 = __ldg(xp + HW_);
                    float n0 = fminf(fmaxf(xv0 + dx0, -1.0f), 1.0f);
                    float n1 = fminf(fmaxf(xv1 + dx1, -1.0f), 1.0f);
                    if (r == 1) n1 = fmaxf(n1, 0.0f);
                    float* op = out + (size_t)bz * (C_ * HW_)
                              + (size_t)(2 * r) * HW_ + (size_t)yy * W_ + g;
                    op[0]   = n0;
                    op[HW_] = n1;
                }
            __syncwarp();
        }
    }
}

extern "C" void kernel_launch(void* const* d_in, const int* in_sizes, int n_in,
                              void* d_out, int out_size)
{
    const float* x  = (const float*)d_in[0];
    const float* w1 = (const float*)d_in[1];
    const float* b1 = (const float*)d_in[2];
    const float* w2 = (const float*)d_in[3];
    const float* b2 = (const float*)d_in[4];
    const float* w3 = (const float*)d_in[5];
    const float* b3 = (const float*)d_in[6];
    const float* gr = (const float*)d_in[7];
    float* out = (float*)d_out;

    k_main<<<PGRID, 128>>>(x, w1, b1, w2, b2, w3, b3, gr, out);
}

// round 7
// speedup vs baseline: 3.6307x; 1.0578x over previous
#include <cuda_runtime.h>
#include <cuda_fp16.h>

typedef unsigned int u32;

#define B_    16
#define C_    8
#define H_    512
#define W_    512
#define HW_   (H_*W_)
#define NPIX  (B_*HW_)
#define PGRID 592          // 4 CTAs x 148 SMs, all co-resident
#define NTILE (B_*H_)      // 8192 row-tiles

__device__ u32 g_cnt;
__device__ u32 g_arr;
__device__ u32 g_dep;

__device__ __forceinline__ u32 pkh(float lo, float hi) {
    __half2 h = __floats2half2_rn(lo, hi);
    return *reinterpret_cast<u32*>(&h);
}
__device__ __forceinline__ u32 pkhr(float lo, float hi) {   // relu + pack
    __half2 h = __floats2half2_rn(fmaxf(lo, 0.0f), fmaxf(hi, 0.0f));
    return *reinterpret_cast<u32*>(&h);
}

// M=pixels, N=outputs: A = activations, B = weights (persistent regs)
__device__ __forceinline__ void mma16(float* d, u32 a0, u32 a1, u32 a2, u32 a3,
                                      u32 b0, u32 b1) {
    asm volatile(
        "mma.sync.aligned.m16n8k16.row.col.f32.f16.f16.f32 "
        "{%0,%1,%2,%3},{%4,%5,%6,%7},{%8,%9},{%0,%1,%2,%3};"
        : "+f"(d[0]), "+f"(d[1]), "+f"(d[2]), "+f"(d[3])
        : "r"(a0), "r"(a1), "r"(a2), "r"(a3), "r"(b0), "r"(b1));
}

__device__ __forceinline__ int swz(int px, int w) {
    return px * 20 + (w ^ ((px >> 3) & 15));
}

__device__ __forceinline__ void loadrow(const float* p, bool okRow, bool okL, bool okR,
                                        int lane, float4& v, float& l, float& r) {
    v = okRow ? __ldg(reinterpret_cast<const float4*>(p)) : make_float4(0.f, 0.f, 0.f, 0.f);
    l = __shfl_up_sync(0xffffffffu, v.w, 1);
    r = __shfl_down_sync(0xffffffffu, v.x, 1);
    if (lane == 0)  l = (okRow && okL) ? __ldg(p - 1) : 0.0f;
    if (lane == 31) r = (okRow && okR) ? __ldg(p + 4) : 0.0f;
}

__global__ void __launch_bounds__(128, 4)
k_main(const float* __restrict__ x,
       const float* __restrict__ w1, const float* __restrict__ b1,
       const float* __restrict__ w2, const float* __restrict__ b2,
       const float* __restrict__ w3, const float* __restrict__ b3,
       const float* __restrict__ growth,
       float* __restrict__ out)
{
    __shared__ __align__(16) u32 sbuf[4 * 128 * 20];   // 40 KB
    __shared__ u32 s_part;
    __shared__ float s_bbase;

    const int tid  = threadIdx.x;
    const int wid  = tid >> 5;
    const int lane = tid & 31;
    const int q = lane >> 2;
    const int r = lane & 3;
    u32* bw = sbuf + wid * (128 * 20);

    // ================= Phase A: global alive count =================
    if (tid == 0) s_part = 0u;
    __syncthreads();
    {
        u32 cnt = 0;
        for (int b = 0; b < B_; b++) {
            const float4* p = reinterpret_cast<const float4*>(
                x + (size_t)b * (C_ * HW_) + (size_t)3 * HW_);
            for (int i = blockIdx.x * 128 + tid; i < HW_ / 4; i += PGRID * 128) {
                float4 v = __ldg(p + i);
                cnt += (v.x > 0.1f) + (v.y > 0.1f) + (v.z > 0.1f) + (v.w > 0.1f);
            }
        }
        #pragma unroll
        for (int o = 16; o; o >>= 1) cnt += __shfl_down_sync(0xffffffffu, cnt, o);
        if (lane == 0) atomicAdd(&s_part, cnt);
    }
    __syncthreads();
    if (tid == 0) {
        atomicAdd(&g_cnt, s_part);
        __threadfence();
        atomicAdd(&g_arr, 1u);
    }
    {
        volatile u32* va = &g_arr;
        while (*va < PGRID) __nanosleep(128);
    }
    __threadfence();
    if (tid == 0) {
        u32 total = *((volatile u32*)&g_cnt);
        s_bbase = ((float)total < 0.2f * (float)NPIX) ? 0.2f : 0.0f;
    }
    __syncthreads();
    const float bbase = s_bbase;
    if (tid == 0) {
        u32 d = atomicAdd(&g_dep, 1u);
        if (d == PGRID - 1) {
            g_cnt = 0u; g_arr = 0u; g_dep = 0u;
            __threadfence();
        }
    }

    // ================= persistent weight fragments =================
    u32 W1f[4][2][2];
    #pragma unroll
    for (int nt = 0; nt < 4; nt++)
        #pragma unroll
        for (int kt = 0; kt < 2; kt++) {
            const float* wr = w1 + (8 * nt + q) * 24;
            int k0 = 16 * kt + 2 * r;
            W1f[nt][kt][0] = pkh(__ldg(&wr[k0]), __ldg(&wr[k0 + 1]));
            W1f[nt][kt][1] = (kt == 0)
                ? pkh(__ldg(&wr[k0 + 8]), __ldg(&wr[k0 + 9])) : 0u;
        }
    u32 W2f[4][2][2];
    #pragma unroll
    for (int nt = 0; nt < 4; nt++)
        #pragma unroll
        for (int kt = 0; kt < 2; kt++) {
            const float* wr = w2 + (8 * nt + q) * 32;
            int k0 = 16 * kt + 2 * r;
            W2f[nt][kt][0] = pkh(__ldg(&wr[k0]), __ldg(&wr[k0 + 1]));
            W2f[nt][kt][1] = pkh(__ldg(&wr[k0 + 8]), __ldg(&wr[k0 + 9]));
        }
    u32 W3f[2][2];
    #pragma unroll
    for (int kt = 0; kt < 2; kt++) {
        const float* wr = w3 + q * 32;
        int k0 = 16 * kt + 2 * r;
        W3f[kt][0] = pkh(__ldg(&wr[k0]), __ldg(&wr[k0 + 1]));
        W3f[kt][1] = pkh(__ldg(&wr[k0 + 8]), __ldg(&wr[k0 + 9]));
    }
    float bA1[4], bB1[4], bA2[4], bB2[4];
    #pragma unroll
    for (int nt = 0; nt < 4; nt++) {
        bA1[nt] = __ldg(&b1[8 * nt + 2 * r]); bB1[nt] = __ldg(&b1[8 * nt + 2 * r + 1]);
        bA2[nt] = __ldg(&b2[8 * nt + 2 * r]); bB2[nt] = __ldg(&b2[8 * nt + 2 * r + 1]);
    }
    const float bA3 = __ldg(&b3[2 * r]), bB3 = __ldg(&b3[2 * r + 1]);
    const float gr  = __ldg(&growth[0]);
    const float AT  = 0.1f;

    // k-pad words 12..15 stay zero forever now (no smem h-stores)
    #pragma unroll
    for (int i = 0; i < 4; i++) {
        int px = 4 * lane + i;
        bw[swz(px, 12)] = 0u; bw[swz(px, 13)] = 0u;
        bw[swz(px, 14)] = 0u; bw[swz(px, 15)] = 0u;
    }

    // ================= Phase B: persistent tile loop =================
    for (int t = blockIdx.x; t < NTILE; t += PGRID) {
        const int yy = t & (H_ - 1);
        const int bz = t >> 9;
        const int x0 = wid * 128;
        const float* xb = x + (size_t)bz * (C_ * HW_);

        const bool okT = (yy > 0), okB = (yy < H_ - 1);
        const bool okL = (x0 > 0), okR = (x0 + 128 < W_);

        __syncwarp();   // prior chunk's layer-1 LDS done before overwriting pbuf

        // ---- perceive ----
        u32 bm0 = 0, bm1 = 0, bm2 = 0, bm3 = 0;
        #pragma unroll
        for (int p = 0; p < 4; p++) {
            float m0v[4], sx0[4], sy0[4];
            float m1v[4], sx1[4], sy1[4];
            bool alive_px[4] = {false, false, false, false};
            #pragma unroll
            for (int sub = 0; sub < 2; sub++) {
                const int ch = 2 * p + sub;
                const float* base = xb + (size_t)ch * HW_ + (size_t)yy * W_ + x0 + 4 * lane;
                float4 tt, mm, bb; float tl, tr, ml, mr, bl, br;
                loadrow(base - W_, okT,  okL, okR, lane, tt, tl, tr);
                loadrow(base,      true, okL, okR, lane, mm, ml, mr);
                loadrow(base + W_, okB,  okL, okR, lane, bb, bl, br);

                float nt_[6] = {tl, tt.x, tt.y, tt.z, tt.w, tr};
                float nm_[6] = {ml, mm.x, mm.y, mm.z, mm.w, mr};
                float nb_[6] = {bl, bb.x, bb.y, bb.z, bb.w, br};

                float* mv = sub ? m1v : m0v;
                float* sx = sub ? sx1 : sx0;
                float* sy = sub ? sy1 : sy0;
                #pragma unroll
                for (int i = 0; i < 4; i++) {
                    mv[i] = nm_[i + 1];
                    sx[i] = (nt_[i + 2] - nt_[i]) + 2.0f * (nm_[i + 2] - nm_[i])
                          + (nb_[i + 2] - nb_[i]);
                    sy[i] = (nb_[i] + 2.0f * nb_[i + 1] + nb_[i + 2])
                          - (nt_[i] + 2.0f * nt_[i + 1] + nt_[i + 2]);
                }
                if (p == 1 && sub == 1) {
                    bool a[6];
                    #pragma unroll
                    for (int j = 0; j < 6; j++)
                        a[j] = (nt_[j] > AT) | (nm_[j] > AT) | (nb_[j] > AT);
                    #pragma unroll
                    for (int i = 0; i < 4; i++)
                        alive_px[i] = a[i] | a[i + 1] | a[i + 2];
                }
            }
            #pragma unroll
            for (int i = 0; i < 4; i++) {
                int px = 4 * lane + i;
                bw[swz(px, p)]     = pkh(m0v[i], m1v[i]);
                bw[swz(px, 4 + p)] = pkh(sx0[i], sx1[i]);
                bw[swz(px, 8 + p)] = pkh(sy0[i], sy1[i]);
            }
            if (p == 1) {
                bm0 = __ballot_sync(0xffffffffu, alive_px[0]);
                bm1 = __ballot_sync(0xffffffffu, alive_px[1]);
                bm2 = __ballot_sync(0xffffffffu, alive_px[2]);
                bm3 = __ballot_sync(0xffffffffu, alive_px[3]);
            }
        }
        __syncwarp();

        const u32 bmsel = (q & 2) ? ((q & 1) ? bm3 : bm2) : ((q & 1) ? bm1 : bm0);

        // ---- 4 chunks of 32 px; layers chained entirely in registers ----
        #pragma unroll
        for (int cidx = 0; cidx < 4; cidx++) {
            const int P = 32 * cidx;

            // Layer 1: A-frags from smem (only smem crossing)
            float d1[2][4][4];
            #pragma unroll
            for (int mt = 0; mt < 2; mt++)
                #pragma unroll
                for (int nt = 0; nt < 4; nt++) {
                    d1[mt][nt][0] = bA1[nt]; d1[mt][nt][1] = bB1[nt];
                    d1[mt][nt][2] = bA1[nt]; d1[mt][nt][3] = bB1[nt];
                }
            #pragma unroll
            for (int kt = 0; kt < 2; kt++)
                #pragma unroll
                for (int mt = 0; mt < 2; mt++) {
                    int px = P + 16 * mt + q;
                    u32 a0 = bw[swz(px,     8 * kt + r)];
                    u32 a1 = bw[swz(px + 8, 8 * kt + r)];
                    u32 a2 = bw[swz(px,     8 * kt + r + 4)];
                    u32 a3 = bw[swz(px + 8, 8 * kt + r + 4)];
                    #pragma unroll
                    for (int nt = 0; nt < 4; nt++)
                        mma16(d1[mt][nt], a0, a1, a2, a3, W1f[nt][kt][0], W1f[nt][kt][1]);
                }

            // Layer 1 -> 2 transition: pure in-register relu+pack
            // A-frag(kt): a0=(px q, ch 16kt+2r)=d1[mt][2kt]c0,c1 ; a1=(px q+8)=c2,c3
            //             a2=(px q, ch 16kt+8+2r)=d1[mt][2kt+1]c0,c1 ; a3=c2,c3
            float d2[2][4][4];
            #pragma unroll
            for (int mt = 0; mt < 2; mt++)
                #pragma unroll
                for (int nt = 0; nt < 4; nt++) {
                    d2[mt][nt][0] = bA2[nt]; d2[mt][nt][1] = bB2[nt];
                    d2[mt][nt][2] = bA2[nt]; d2[mt][nt][3] = bB2[nt];
                }
            #pragma unroll
            for (int mt = 0; mt < 2; mt++)
                #pragma unroll
                for (int kt = 0; kt < 2; kt++) {
                    u32 a0 = pkhr(d1[mt][2 * kt][0],     d1[mt][2 * kt][1]);
                    u32 a1 = pkhr(d1[mt][2 * kt][2],     d1[mt][2 * kt][3]);
                    u32 a2 = pkhr(d1[mt][2 * kt + 1][0], d1[mt][2 * kt + 1][1]);
                    u32 a3 = pkhr(d1[mt][2 * kt + 1][2], d1[mt][2 * kt + 1][3]);
                    #pragma unroll
                    for (int nt = 0; nt < 4; nt++)
                        mma16(d2[mt][nt], a0, a1, a2, a3, W2f[nt][kt][0], W2f[nt][kt][1]);
                }

            // Layer 2 -> 3 transition + layer 3
            float e[2][4];
            #pragma unroll
            for (int mt = 0; mt < 2; mt++) {
                e[mt][0] = bA3; e[mt][1] = bB3; e[mt][2] = bA3; e[mt][3] = bB3;
            }
            #pragma unroll
            for (int mt = 0; mt < 2; mt++)
                #pragma unroll
                for (int kt = 0; kt < 2; kt++) {
                    u32 a0 = pkhr(d2[mt][2 * kt][0],     d2[mt][2 * kt][1]);
                    u32 a1 = pkhr(d2[mt][2 * kt][2],     d2[mt][2 * kt][3]);
                    u32 a2 = pkhr(d2[mt][2 * kt + 1][0], d2[mt][2 * kt + 1][1]);
                    u32 a3 = pkhr(d2[mt][2 * kt + 1][2], d2[mt][2 * kt + 1][3]);
                    mma16(e[mt], a0, a1, a2, a3, W3f[kt][0], W3f[kt][1]);
                }

            // epilogue: lane(q,r) holds px {P+16mt+q, +8} x ch {2r, 2r+1}
            #pragma unroll
            for (int mt = 0; mt < 2; mt++)
                #pragma unroll
                for (int h = 0; h < 2; h++) {
                    float e0 = e[mt][2 * h], e1 = e[mt][2 * h + 1];
                    int pxl = P + 16 * mt + 8 * h + q;
                    int g   = x0 + pxl;
                    float dx0 = e0 * gr, dx1 = e1 * gr;
                    if (r == 1) {
                        float bo = ((bmsel >> (pxl >> 2)) & 1u) ? bbase : 0.0f;
                        dx1 += bo;
                    }
                    const float* xp = xb + (size_t)(2 * r) * HW_ + (size_t)yy * W_ + g;
                    float xv0 = __ldg(xp);
                    float xv1 = __ldg(xp + HW_);
                    float n0 = fminf(fmaxf(xv0 + dx0, -1.0f), 1.0f);
                    float n1 = fminf(fmaxf(xv1 + dx1, -1.0f), 1.0f);
                    if (r == 1) n1 = fmaxf(n1, 0.0f);
                    float* op = out + (size_t)bz * (C_ * HW_)
                              + (size_t)(2 * r) * HW_ + (size_t)yy * W_ + g;
                    op[0]   = n0;
                    op[HW_] = n1;
                }
        }
    }
}

extern "C" void kernel_launch(void* const* d_in, const int* in_sizes, int n_in,
                              void* d_out, int out_size)
{
    const float* x  = (const float*)d_in[0];
    const float* w1 = (const float*)d_in[1];
    const float* b1 = (const float*)d_in[2];
    const float* w2 = (const float*)d_in[3];
    const float* b2 = (const float*)d_in[4];
    const float* w3 = (const float*)d_in[5];
    const float* b3 = (const float*)d_in[6];
    const float* gr = (const float*)d_in[7];
    float* out = (float*)d_out;

    k_main<<<PGRID, 128>>>(x, w1, b1, w2, b2, w3, b3, gr, out);
}